// round 1
// baseline (speedup 1.0000x reference)
#include <cuda_runtime.h>
#include <cuda_bf16.h>
#include <math.h>

// ---------------- problem constants ----------------
#define S       2048
#define HID     2048
#define NH      16
#define NKV     8
#define HD      128
#define QDIM    (NH*HD)    // 2048
#define KVDIM   (NKV*HD)   // 1024

// ---------------- scratch (no cudaMalloc allowed) ----------------
__device__ float g_Q[S * QDIM];
__device__ float g_K[S * KVDIM];
__device__ float g_V[S * KVDIM];
__device__ float g_ctx[S * QDIM];

// ============================================================
// Tiled SGEMM:  C[m,n] = sum_k A[m*K+k] * B[n*K+k]   (both K-major)
// 128x128 tile, 256 threads, 8x8 microtile, k-tile 16.
// ============================================================
#define GT 128
#define GK 16
#define GPAD 4

__global__ __launch_bounds__(256) void gemm_nt(const float* __restrict__ A,
                                               const float* __restrict__ B,
                                               float* __restrict__ C,
                                               int M, int N, int K) {
    __shared__ float As[GK][GT + GPAD];
    __shared__ float Bs[GK][GT + GPAD];
    const int tid = threadIdx.x;
    const int m0 = blockIdx.y * GT;
    const int n0 = blockIdx.x * GT;
    const int tx = tid & 15;          // 0..15 -> n microtile
    const int ty = tid >> 4;          // 0..15 -> m microtile

    float acc[8][8];
#pragma unroll
    for (int i = 0; i < 8; i++)
#pragma unroll
        for (int j = 0; j < 8; j++) acc[i][j] = 0.f;

    for (int k0 = 0; k0 < K; k0 += GK) {
        // load 128 rows x 16 k of A and B (512 float4 each), transposed into smem
#pragma unroll
        for (int l = 0; l < 2; l++) {
            int idx = tid + l * 256;          // 0..511
            int row = idx >> 2;
            int k4  = (idx & 3) * 4;
            float4 va = *(const float4*)(A + (m0 + row) * K + k0 + k4);
            As[k4 + 0][row] = va.x; As[k4 + 1][row] = va.y;
            As[k4 + 2][row] = va.z; As[k4 + 3][row] = va.w;
            float4 vb = *(const float4*)(B + (n0 + row) * K + k0 + k4);
            Bs[k4 + 0][row] = vb.x; Bs[k4 + 1][row] = vb.y;
            Bs[k4 + 2][row] = vb.z; Bs[k4 + 3][row] = vb.w;
        }
        __syncthreads();

#pragma unroll
        for (int k = 0; k < GK; k++) {
            float a[8], b[8];
#pragma unroll
            for (int i = 0; i < 8; i++) a[i] = As[k][ty * 8 + i];
#pragma unroll
            for (int j = 0; j < 8; j++) b[j] = Bs[k][tx * 8 + j];
#pragma unroll
            for (int i = 0; i < 8; i++)
#pragma unroll
                for (int j = 0; j < 8; j++)
                    acc[i][j] = fmaf(a[i], b[j], acc[i][j]);
        }
        __syncthreads();
    }

#pragma unroll
    for (int i = 0; i < 8; i++) {
        float* cp = C + (m0 + ty * 8 + i) * N + n0 + tx * 8;
#pragma unroll
        for (int j = 0; j < 8; j += 4) {
            float4 v = make_float4(acc[i][j], acc[i][j + 1], acc[i][j + 2], acc[i][j + 3]);
            *(float4*)(cp + j) = v;
        }
    }
}

// ============================================================
// RoPE + RMS-norm (in place). One block per (seq pos, head), 64 threads.
// Reference order: rope first, then rms_norm over 128 dims.
// ============================================================
__global__ void rope_rms(float* __restrict__ X, const float* __restrict__ w,
                         const int* __restrict__ pos_ids, int rowstride) {
    const int s = blockIdx.x;
    const int h = blockIdx.y;
    const int d = threadIdx.x;            // 0..63 (pair d, d+64)
    float* x = X + s * rowstride + h * HD;

    float pos = (float)pos_ids[s];
    // inv_freq = THETA^(-d/64); log2(1e6) = 19.93156856932417...
    const float NL2T_64 = 19.931568569324174f / 64.0f;
    float inv = exp2f(-(float)d * NL2T_64);
    float f = pos * inv;
    float sn, c;
    sincosf(f, &sn, &c);

    float x1 = x[d], x2 = x[d + 64];
    float o1 = x1 * c - x2 * sn;
    float o2 = x2 * c + x1 * sn;

    // mean of squares over 128 values
    float sq = o1 * o1 + o2 * o2;
#pragma unroll
    for (int off = 16; off; off >>= 1) sq += __shfl_xor_sync(0xffffffffu, sq, off);
    __shared__ float wsum[2];
    if ((threadIdx.x & 31) == 0) wsum[threadIdx.x >> 5] = sq;
    __syncthreads();
    float var = (wsum[0] + wsum[1]) * (1.0f / 128.0f);
    float r = rsqrtf(var + 1e-6f);

    x[d]      = o1 * r * w[d];
    x[d + 64] = o2 * r * w[d + 64];
}

// ============================================================
// Causal GQA flash attention, fp32.
// grid (S/32 qtiles, NH heads), 128 threads.
// Thread t: query row (t>>2) of the tile, dim slice {4j + (t&3)}.
// ============================================================
#define QT 32
#define KT 32

__global__ __launch_bounds__(128) void attn(const float* __restrict__ Q,
                                            const float* __restrict__ K,
                                            const float* __restrict__ V,
                                            float* __restrict__ ctx) {
    __shared__ float Ks[KT][HD];
    __shared__ float Vs[KT][HD];

    const int qt = (gridDim.x - 1) - blockIdx.x;   // heavy tiles first
    const int h  = blockIdx.y;
    const int kh = h >> 1;                          // GQA: 2 Q heads per KV head
    const int tid = threadIdx.x;
    const int qr   = tid >> 2;                      // 0..31
    const int quad = tid & 3;                       // 0..3
    const int qi   = qt * QT + qr;                  // global query index

    const float scale = 0.08838834764831845f;       // 1/sqrt(128)

    // cache scaled q slice: dims 4j+quad
    float qreg[32];
    {
        const float* qp = Q + qi * QDIM + h * HD;
#pragma unroll
        for (int j = 0; j < 32; j++) qreg[j] = qp[j * 4 + quad] * scale;
    }

    float O[32];
#pragma unroll
    for (int j = 0; j < 32; j++) O[j] = 0.f;
    float m = -1e30f, l = 0.f;

    const int ntiles = qt + 1;                      // causal
    for (int kt = 0; kt < ntiles; kt++) {
        const int k0 = kt * KT;
        // cooperative load of K/V tile (coalesced float4)
        {
            const float4* kg = (const float4*)(K + k0 * KVDIM + kh * HD);
            const float4* vg = (const float4*)(V + k0 * KVDIM + kh * HD);
            float4* ks = (float4*)&Ks[0][0];
            float4* vs = (float4*)&Vs[0][0];
            const int gstride = KVDIM / 4;          // float4 per global row
#pragma unroll
            for (int i = 0; i < 8; i++) {
                int idx = tid + i * 128;            // 0..1023
                int row = idx >> 5;                  // /32 float4 per tile row
                int c4  = idx & 31;
                ks[row * 32 + c4] = kg[row * gstride + c4];
                vs[row * 32 + c4] = vg[row * gstride + c4];
            }
        }
        __syncthreads();

        // scores for 32 keys
        float sc[KT];
        float tmax = -1e30f;
#pragma unroll 4
        for (int kj = 0; kj < KT; kj++) {
            float p = 0.f;
            const float* kr = &Ks[kj][quad];
#pragma unroll
            for (int j = 0; j < 32; j++) p = fmaf(qreg[j], kr[j * 4], p);
            p += __shfl_xor_sync(0xffffffffu, p, 1);
            p += __shfl_xor_sync(0xffffffffu, p, 2);
            float s = (k0 + kj <= qi) ? p : -1e30f;
            sc[kj] = s;
            tmax = fmaxf(tmax, s);
        }

        // online softmax update
        float mnew = fmaxf(m, tmax);
        float alpha = __expf(m - mnew);
        l *= alpha;
#pragma unroll
        for (int j = 0; j < 32; j++) O[j] *= alpha;
#pragma unroll 4
        for (int kj = 0; kj < KT; kj++) {
            float p = __expf(sc[kj] - mnew);
            l += p;
            const float* vr = &Vs[kj][quad];
#pragma unroll
            for (int j = 0; j < 32; j++) O[j] = fmaf(p, vr[j * 4], O[j]);
        }
        m = mnew;
        __syncthreads();
    }

    float rl = 1.0f / l;
    float* cp = ctx + qi * QDIM + h * HD;
#pragma unroll
    for (int j = 0; j < 32; j++) cp[j * 4 + quad] = O[j] * rl;
}

// ============================================================
// launch
// inputs: 0 hidden_states [1,2048,2048] f32
//         1 attention_mask (unused; structural causal)
//         2 position_ids int32 [1,2048]
//         3 wq [2048,2048]  4 wk [1024,2048]  5 wv [1024,2048]
//         6 wo [2048,2048]  7 q_norm_w [128]  8 k_norm_w [128]
// output: [1,2048,2048] f32
// ============================================================
extern "C" void kernel_launch(void* const* d_in, const int* in_sizes, int n_in,
                              void* d_out, int out_size) {
    const float* X   = (const float*)d_in[0];
    const int*   pos = (const int*)d_in[2];
    const float* wq  = (const float*)d_in[3];
    const float* wk  = (const float*)d_in[4];
    const float* wv  = (const float*)d_in[5];
    const float* wo  = (const float*)d_in[6];
    const float* qnw = (const float*)d_in[7];
    const float* knw = (const float*)d_in[8];
    float* out = (float*)d_out;

    float *Q, *Kb, *Vb, *ctx;
    cudaGetSymbolAddress((void**)&Q,   g_Q);
    cudaGetSymbolAddress((void**)&Kb,  g_K);
    cudaGetSymbolAddress((void**)&Vb,  g_V);
    cudaGetSymbolAddress((void**)&ctx, g_ctx);

    // projections
    gemm_nt<<<dim3(QDIM / GT,  S / GT), 256>>>(X, wq, Q,  S, QDIM,  HID);
    gemm_nt<<<dim3(KVDIM / GT, S / GT), 256>>>(X, wk, Kb, S, KVDIM, HID);
    gemm_nt<<<dim3(KVDIM / GT, S / GT), 256>>>(X, wv, Vb, S, KVDIM, HID);

    // rope + rms (in place)
    rope_rms<<<dim3(S, NH),  64>>>(Q,  qnw, pos, QDIM);
    rope_rms<<<dim3(S, NKV), 64>>>(Kb, knw, pos, KVDIM);

    // attention
    attn<<<dim3(S / QT, NH), 128>>>(Q, Kb, Vb, ctx);

    // output projection
    gemm_nt<<<dim3(QDIM / GT, S / GT), 256>>>(ctx, wo, out, S, QDIM, HID);
}

// round 3
// speedup vs baseline: 1.5182x; 1.5182x over previous
#include <cuda_runtime.h>
#include <cuda_bf16.h>
#include <cstdint>
#include <math.h>

// ---------------- problem constants ----------------
#define S       2048
#define HID     2048
#define NH      16
#define NKV     8
#define HD      128
#define QDIM    (NH*HD)    // 2048
#define KVDIM   (NKV*HD)   // 1024
#define KTOT    2048

// ---------------- scratch (no cudaMalloc allowed) ----------------
__device__ float g_Q[S * QDIM];
__device__ float g_K[S * KVDIM];
__device__ float g_V[S * KVDIM];
__device__ float g_ctx[S * QDIM];

__device__ __nv_bfloat16 g_Xhi[S * HID],      g_Xlo[S * HID];
__device__ __nv_bfloat16 g_Wqhi[QDIM * HID],  g_Wqlo[QDIM * HID];
__device__ __nv_bfloat16 g_Wkhi[KVDIM * HID], g_Wklo[KVDIM * HID];
__device__ __nv_bfloat16 g_Wvhi[KVDIM * HID], g_Wvlo[KVDIM * HID];
__device__ __nv_bfloat16 g_Wohi[HID * QDIM],  g_Wolo[HID * QDIM];
__device__ __nv_bfloat16 g_Chi[S * QDIM],     g_Clo[S * QDIM];

// ================= PTX helpers (sm_80-era, valid on base sm_103) =================
__device__ __forceinline__ uint32_t smem_u32(const void* p) {
    uint32_t a;
    asm("{ .reg .u64 t; cvta.to.shared.u64 t, %1; cvt.u32.u64 %0, t; }" : "=r"(a) : "l"(p));
    return a;
}
__device__ __forceinline__ void cpasync16(uint32_t s, const void* g) {
    asm volatile("cp.async.cg.shared.global [%0], [%1], 16;" :: "r"(s), "l"(g));
}
__device__ __forceinline__ void ldsm4(uint32_t* r, uint32_t addr) {
    asm volatile("ldmatrix.sync.aligned.m8n8.x4.shared.b16 {%0,%1,%2,%3}, [%4];"
                 : "=r"(r[0]), "=r"(r[1]), "=r"(r[2]), "=r"(r[3]) : "r"(addr));
}
__device__ __forceinline__ void mma16816(float* c, const uint32_t* a, const uint32_t* b) {
    asm volatile(
        "mma.sync.aligned.m16n8k16.row.col.f32.bf16.bf16.f32 "
        "{%0,%1,%2,%3}, {%4,%5,%6,%7}, {%8,%9}, {%0,%1,%2,%3};"
        : "+f"(c[0]), "+f"(c[1]), "+f"(c[2]), "+f"(c[3])
        : "r"(a[0]), "r"(a[1]), "r"(a[2]), "r"(a[3]), "r"(b[0]), "r"(b[1]));
}

// ============================================================
// fp32 -> (hi, lo) bf16 split.
// ============================================================
__global__ void split_bf16(const float* __restrict__ x,
                           __nv_bfloat16* __restrict__ hi,
                           __nv_bfloat16* __restrict__ lo, int n4) {
    int i = blockIdx.x * blockDim.x + threadIdx.x;
    if (i >= n4) return;
    float4 v = ((const float4*)x)[i];
    __nv_bfloat16 h0 = __float2bfloat16(v.x), h1 = __float2bfloat16(v.y);
    __nv_bfloat16 h2 = __float2bfloat16(v.z), h3 = __float2bfloat16(v.w);
    __nv_bfloat16 l0 = __float2bfloat16(v.x - __bfloat162float(h0));
    __nv_bfloat16 l1 = __float2bfloat16(v.y - __bfloat162float(h1));
    __nv_bfloat16 l2 = __float2bfloat16(v.z - __bfloat162float(h2));
    __nv_bfloat16 l3 = __float2bfloat16(v.w - __bfloat162float(h3));
    __nv_bfloat162* H = (__nv_bfloat162*)hi;
    __nv_bfloat162* L = (__nv_bfloat162*)lo;
    H[2 * i]     = __halves2bfloat162(h0, h1);
    H[2 * i + 1] = __halves2bfloat162(h2, h3);
    L[2 * i]     = __halves2bfloat162(l0, l1);
    L[2 * i + 1] = __halves2bfloat162(l2, l3);
}

// ============================================================
// mma.sync bf16 split GEMM: C[m,n] = sum_k A[m,k]*B[n,k], K=2048.
// CTA 128x128x32, 256 threads (8 warps, 2m x 4n), warp tile 64x32.
// 3 products (AhBh + AhBl + AlBh) share one fp32 accumulator.
// cp.async double-buffered, XOR-swizzled smem (conflict-free ldmatrix).
// ============================================================
#define BM 128
#define BN 128
#define BK 32
#define NIT (KTOT / BK)          // 64
#define TILEB (BM * 64)          // 8KB (128 rows * 32 bf16)
#define STAGEB (4 * TILEB)       // Ahi,Alo,Bhi,Blo = 32KB
#define GSMEM (2 * STAGEB)       // 64KB

// swizzled byte offset within a tile: row, 16B-chunk ci (0..3)
__device__ __forceinline__ uint32_t swz(int row, int ci) {
    return (uint32_t)(row * 64 + ((ci ^ ((row >> 1) & 3)) << 4));
}

__global__ __launch_bounds__(256, 1)
void gemm_mma(const __nv_bfloat16* __restrict__ Ahi, const __nv_bfloat16* __restrict__ Alo,
              const __nv_bfloat16* __restrict__ Bhi, const __nv_bfloat16* __restrict__ Blo,
              float* __restrict__ C, int N) {
    extern __shared__ char smem[];
    const uint32_t sb = smem_u32(smem);
    const int tid = threadIdx.x;
    const int lane = tid & 31;
    const int w = tid >> 5;
    const int wm = w & 1;            // 2 m-groups of 64
    const int wn = w >> 1;           // 4 n-groups of 32
    const int m0 = blockIdx.y * BM;
    const int n0 = blockIdx.x * BN;

    // ---- ldmatrix lane offsets (within stage, kc=0) ----
    const int arow_l = (lane & 7) + ((lane >> 3) & 1) * 8;
    const int ahi_c  = lane >> 4;
    const int brow_l = (lane & 7) + ((lane >> 4) & 1) * 8;
    const int bhi_c  = (lane >> 3) & 1;
    uint32_t aoff[4], boff[2];
#pragma unroll
    for (int mi = 0; mi < 4; mi++) {
        int row = wm * 64 + mi * 16 + arow_l;
        aoff[mi] = swz(row, ahi_c);
    }
#pragma unroll
    for (int nt = 0; nt < 2; nt++) {
        int row = wn * 32 + nt * 16 + brow_l;
        boff[nt] = 2 * TILEB + swz(row, bhi_c);
    }

    // ---- global load lane mapping ----
    const int grow = tid >> 2;        // 0..63 (+pass*64)
    const int gci  = tid & 3;
    const size_t krow = (size_t)KTOT;

    float acc[4][4][4];
#pragma unroll
    for (int mi = 0; mi < 4; mi++)
#pragma unroll
        for (int ni = 0; ni < 4; ni++)
#pragma unroll
            for (int e = 0; e < 4; e++) acc[mi][ni][e] = 0.f;

    auto load_stage = [&](int it, int buf) {
        const int k0 = it * BK;
        const uint32_t st = sb + buf * STAGEB;
#pragma unroll
        for (int p = 0; p < 2; p++) {
            int row = grow + p * 64;
            uint32_t so = swz(row, gci);
            const __nv_bfloat16* a0 = Ahi + (size_t)(m0 + row) * krow + k0 + gci * 8;
            const __nv_bfloat16* a1 = Alo + (size_t)(m0 + row) * krow + k0 + gci * 8;
            const __nv_bfloat16* b0 = Bhi + (size_t)(n0 + row) * krow + k0 + gci * 8;
            const __nv_bfloat16* b1 = Blo + (size_t)(n0 + row) * krow + k0 + gci * 8;
            cpasync16(st + 0 * TILEB + so, a0);
            cpasync16(st + 1 * TILEB + so, a1);
            cpasync16(st + 2 * TILEB + so, b0);
            cpasync16(st + 3 * TILEB + so, b1);
        }
    };

    load_stage(0, 0);
    asm volatile("cp.async.commit_group;" ::: "memory");

    for (int it = 0; it < NIT; it++) {
        if (it + 1 < NIT) {
            load_stage(it + 1, (it + 1) & 1);
            asm volatile("cp.async.commit_group;" ::: "memory");
            asm volatile("cp.async.wait_group 1;" ::: "memory");
        } else {
            asm volatile("cp.async.wait_group 0;" ::: "memory");
        }
        __syncthreads();

        const uint32_t st = sb + (it & 1) * STAGEB;
#pragma unroll
        for (int kc = 0; kc < 2; kc++) {
            const uint32_t kx = kc << 5;
            uint32_t ah[4][4], al[4][4], bh[4][2], bl[4][2];
#pragma unroll
            for (int mi = 0; mi < 4; mi++) {
                ldsm4(ah[mi], st + (aoff[mi] ^ kx));
                ldsm4(al[mi], st + TILEB + (aoff[mi] ^ kx));
            }
#pragma unroll
            for (int nt = 0; nt < 2; nt++) {
                uint32_t t[4];
                ldsm4(t, st + (boff[nt] ^ kx));
                bh[2 * nt][0] = t[0]; bh[2 * nt][1] = t[1];
                bh[2 * nt + 1][0] = t[2]; bh[2 * nt + 1][1] = t[3];
                ldsm4(t, st + TILEB + (boff[nt] ^ kx));
                bl[2 * nt][0] = t[0]; bl[2 * nt][1] = t[1];
                bl[2 * nt + 1][0] = t[2]; bl[2 * nt + 1][1] = t[3];
            }
#pragma unroll
            for (int mi = 0; mi < 4; mi++)
#pragma unroll
                for (int ni = 0; ni < 4; ni++) {
                    mma16816(acc[mi][ni], ah[mi], bh[ni]);
                    mma16816(acc[mi][ni], ah[mi], bl[ni]);
                    mma16816(acc[mi][ni], al[mi], bh[ni]);
                }
        }
        __syncthreads();
    }

    // ---- epilogue ----
    const int mrow = m0 + wm * 64 + (lane >> 2);
    const int ncol = n0 + wn * 32 + (lane & 3) * 2;
#pragma unroll
    for (int mi = 0; mi < 4; mi++)
#pragma unroll
        for (int ni = 0; ni < 4; ni++) {
            float* c0 = C + (size_t)(mrow + mi * 16) * N + ncol + ni * 8;
            float* c1 = C + (size_t)(mrow + mi * 16 + 8) * N + ncol + ni * 8;
            *(float2*)c0 = make_float2(acc[mi][ni][0], acc[mi][ni][1]);
            *(float2*)c1 = make_float2(acc[mi][ni][2], acc[mi][ni][3]);
        }
}

// ============================================================
// RoPE + RMS-norm (in place). One block per (seq pos, head), 64 threads.
// ============================================================
__global__ void rope_rms(float* __restrict__ X, const float* __restrict__ w,
                         const int* __restrict__ pos_ids, int rowstride) {
    const int s = blockIdx.x;
    const int h = blockIdx.y;
    const int d = threadIdx.x;            // 0..63 (pair d, d+64)
    float* x = X + (size_t)s * rowstride + h * HD;

    float pos = (float)pos_ids[s];
    const float NL2T_64 = 19.931568569324174f / 64.0f;
    float inv = exp2f(-(float)d * NL2T_64);
    float f = pos * inv;
    float sn, c;
    sincosf(f, &sn, &c);

    float x1 = x[d], x2 = x[d + 64];
    float o1 = x1 * c - x2 * sn;
    float o2 = x2 * c + x1 * sn;

    float sq = o1 * o1 + o2 * o2;
#pragma unroll
    for (int off = 16; off; off >>= 1) sq += __shfl_xor_sync(0xffffffffu, sq, off);
    __shared__ float wsum[2];
    if ((threadIdx.x & 31) == 0) wsum[threadIdx.x >> 5] = sq;
    __syncthreads();
    float var = (wsum[0] + wsum[1]) * (1.0f / 128.0f);
    float r = rsqrtf(var + 1e-6f);

    x[d]      = o1 * r * w[d];
    x[d + 64] = o2 * r * w[d + 64];
}

// ============================================================
// Causal GQA flash attention, fp32, float4-vectorized smem reads.
// ============================================================
#define QT 32
#define KT 32

__global__ __launch_bounds__(128) void attn(const float* __restrict__ Q,
                                            const float* __restrict__ K,
                                            const float* __restrict__ V,
                                            float* __restrict__ ctx) {
    __shared__ float Ks[KT][HD];
    __shared__ float Vs[KT][HD];

    const int qt = (gridDim.x - 1) - blockIdx.x;   // heavy tiles first
    const int h  = blockIdx.y;
    const int kh = h >> 1;
    const int tid = threadIdx.x;
    const int qr   = tid >> 2;
    const int quad = tid & 3;
    const int qi   = qt * QT + qr;

    const float scale = 0.08838834764831845f;       // 1/sqrt(128)

    float4 qv[8];
    {
        const float4* qp = (const float4*)(Q + (size_t)qi * QDIM + h * HD);
#pragma unroll
        for (int j = 0; j < 8; j++) {
            float4 v = qp[j * 4 + quad];
            qv[j] = make_float4(v.x * scale, v.y * scale, v.z * scale, v.w * scale);
        }
    }

    float4 O[8];
#pragma unroll
    for (int j = 0; j < 8; j++) O[j] = make_float4(0.f, 0.f, 0.f, 0.f);
    float m = -1e30f, l = 0.f;

    const int ntiles = qt + 1;
    for (int kt = 0; kt < ntiles; kt++) {
        const int k0 = kt * KT;
        {
            const float4* kg = (const float4*)(K + (size_t)k0 * KVDIM + kh * HD);
            const float4* vg = (const float4*)(V + (size_t)k0 * KVDIM + kh * HD);
            float4* ks = (float4*)&Ks[0][0];
            float4* vs = (float4*)&Vs[0][0];
            const int gstride = KVDIM / 4;
#pragma unroll
            for (int i = 0; i < 8; i++) {
                int idx = tid + i * 128;
                int row = idx >> 5;
                int c4  = idx & 31;
                ks[row * 32 + c4] = kg[row * gstride + c4];
                vs[row * 32 + c4] = vg[row * gstride + c4];
            }
        }
        __syncthreads();

        float sc[KT];
        float tmax = -1e30f;
#pragma unroll 4
        for (int kj = 0; kj < KT; kj++) {
            const float4* kr = (const float4*)&Ks[kj][0];
            float p = 0.f;
#pragma unroll
            for (int j = 0; j < 8; j++) {
                float4 kv = kr[j * 4 + quad];
                p = fmaf(qv[j].x, kv.x, p);
                p = fmaf(qv[j].y, kv.y, p);
                p = fmaf(qv[j].z, kv.z, p);
                p = fmaf(qv[j].w, kv.w, p);
            }
            p += __shfl_xor_sync(0xffffffffu, p, 1);
            p += __shfl_xor_sync(0xffffffffu, p, 2);
            float sv = (k0 + kj <= qi) ? p : -1e30f;
            sc[kj] = sv;
            tmax = fmaxf(tmax, sv);
        }

        float mnew = fmaxf(m, tmax);
        float alpha = __expf(m - mnew);
        l *= alpha;
#pragma unroll
        for (int j = 0; j < 8; j++) {
            O[j].x *= alpha; O[j].y *= alpha; O[j].z *= alpha; O[j].w *= alpha;
        }
#pragma unroll 4
        for (int kj = 0; kj < KT; kj++) {
            float p = __expf(sc[kj] - mnew);
            l += p;
            const float4* vr = (const float4*)&Vs[kj][0];
#pragma unroll
            for (int j = 0; j < 8; j++) {
                float4 vv = vr[j * 4 + quad];
                O[j].x = fmaf(p, vv.x, O[j].x);
                O[j].y = fmaf(p, vv.y, O[j].y);
                O[j].z = fmaf(p, vv.z, O[j].z);
                O[j].w = fmaf(p, vv.w, O[j].w);
            }
        }
        m = mnew;
        __syncthreads();
    }

    float rl = 1.0f / l;
    float4* cp = (float4*)(ctx + (size_t)qi * QDIM + h * HD);
#pragma unroll
    for (int j = 0; j < 8; j++) {
        cp[j * 4 + quad] = make_float4(O[j].x * rl, O[j].y * rl, O[j].z * rl, O[j].w * rl);
    }
}

// ============================================================
// launch
// ============================================================
extern "C" void kernel_launch(void* const* d_in, const int* in_sizes, int n_in,
                              void* d_out, int out_size) {
    const float* X   = (const float*)d_in[0];
    const int*   pos = (const int*)d_in[2];
    const float* wq  = (const float*)d_in[3];
    const float* wk  = (const float*)d_in[4];
    const float* wv  = (const float*)d_in[5];
    const float* wo  = (const float*)d_in[6];
    const float* qnw = (const float*)d_in[7];
    const float* knw = (const float*)d_in[8];
    float* out = (float*)d_out;

    float *Q, *Kb, *Vb, *ctx;
    cudaGetSymbolAddress((void**)&Q,   g_Q);
    cudaGetSymbolAddress((void**)&Kb,  g_K);
    cudaGetSymbolAddress((void**)&Vb,  g_V);
    cudaGetSymbolAddress((void**)&ctx, g_ctx);

    __nv_bfloat16 *Xhi, *Xlo, *Wqhi, *Wqlo, *Wkhi, *Wklo, *Wvhi, *Wvlo, *Wohi, *Wolo, *Chi, *Clo;
    cudaGetSymbolAddress((void**)&Xhi,  g_Xhi);  cudaGetSymbolAddress((void**)&Xlo,  g_Xlo);
    cudaGetSymbolAddress((void**)&Wqhi, g_Wqhi); cudaGetSymbolAddress((void**)&Wqlo, g_Wqlo);
    cudaGetSymbolAddress((void**)&Wkhi, g_Wkhi); cudaGetSymbolAddress((void**)&Wklo, g_Wklo);
    cudaGetSymbolAddress((void**)&Wvhi, g_Wvhi); cudaGetSymbolAddress((void**)&Wvlo, g_Wvlo);
    cudaGetSymbolAddress((void**)&Wohi, g_Wohi); cudaGetSymbolAddress((void**)&Wolo, g_Wolo);
    cudaGetSymbolAddress((void**)&Chi,  g_Chi);  cudaGetSymbolAddress((void**)&Clo,  g_Clo);

    cudaFuncSetAttribute(gemm_mma, cudaFuncAttributeMaxDynamicSharedMemorySize, GSMEM);

    // fp32 -> hi/lo bf16 splits
    const int T = 256;
    split_bf16<<<(S * HID / 4 + T - 1) / T, T>>>(X,  Xhi,  Xlo,  S * HID / 4);
    split_bf16<<<(QDIM * HID / 4 + T - 1) / T, T>>>(wq, Wqhi, Wqlo, QDIM * HID / 4);
    split_bf16<<<(KVDIM * HID / 4 + T - 1) / T, T>>>(wk, Wkhi, Wklo, KVDIM * HID / 4);
    split_bf16<<<(KVDIM * HID / 4 + T - 1) / T, T>>>(wv, Wvhi, Wvlo, KVDIM * HID / 4);
    split_bf16<<<(HID * QDIM / 4 + T - 1) / T, T>>>(wo, Wohi, Wolo, HID * QDIM / 4);

    // projections on tensor cores (mma.sync)
    gemm_mma<<<dim3(QDIM / BN,  S / BM), 256, GSMEM>>>(Xhi, Xlo, Wqhi, Wqlo, Q,  QDIM);
    gemm_mma<<<dim3(KVDIM / BN, S / BM), 256, GSMEM>>>(Xhi, Xlo, Wkhi, Wklo, Kb, KVDIM);
    gemm_mma<<<dim3(KVDIM / BN, S / BM), 256, GSMEM>>>(Xhi, Xlo, Wvhi, Wvlo, Vb, KVDIM);

    // rope + rms (in place)
    rope_rms<<<dim3(S, NH),  64>>>(Q,  qnw, pos, QDIM);
    rope_rms<<<dim3(S, NKV), 64>>>(Kb, knw, pos, KVDIM);

    // attention
    attn<<<dim3(S / QT, NH), 128>>>(Q, Kb, Vb, ctx);

    // output projection
    split_bf16<<<(S * QDIM / 4 + T - 1) / T, T>>>(ctx, Chi, Clo, S * QDIM / 4);
    gemm_mma<<<dim3(QDIM / BN, S / BM), 256, GSMEM>>>(Chi, Clo, Wohi, Wolo, out, QDIM);
}

// round 8
// speedup vs baseline: 8.0989x; 5.3346x over previous
#include <cuda_runtime.h>
#include <cuda_fp16.h>
#include <cstdint>
#include <math.h>

// ---------------- problem constants ----------------
#define S       2048
#define HID     2048
#define NH      16
#define NKV     8
#define HD      128
#define QDIM    (NH*HD)    // 2048
#define KVDIM   (NKV*HD)   // 1024
#define KTOT    2048

// ---------------- scratch (no cudaMalloc allowed) ----------------
__device__ float g_Q[S * QDIM];
__device__ float g_K[S * KVDIM];
__device__ float g_V[S * KVDIM];

__device__ __half g_Xh[S * HID];
__device__ __half g_Wqh[QDIM * HID];
__device__ __half g_Wkh[KVDIM * HID];
__device__ __half g_Wvh[KVDIM * HID];
__device__ __half g_Woh[HID * QDIM];
__device__ __half g_Qh[S * QDIM];
__device__ __half g_Kh[S * KVDIM];
__device__ __half g_Vh[S * KVDIM];
__device__ __half g_Ch[S * QDIM];

// ================= PTX helpers (sm_80-era, valid on base sm_103) =================
__device__ __forceinline__ uint32_t smem_u32(const void* p) {
    uint32_t a;
    asm("{ .reg .u64 t; cvta.to.shared.u64 t, %1; cvt.u32.u64 %0, t; }" : "=r"(a) : "l"(p));
    return a;
}
__device__ __forceinline__ uint32_t h2u(__half2 h) {
    return *reinterpret_cast<uint32_t*>(&h);
}
__device__ __forceinline__ void cpasync16(uint32_t s, const void* g) {
    asm volatile("cp.async.cg.shared.global [%0], [%1], 16;" :: "r"(s), "l"(g));
}
__device__ __forceinline__ void ldsm4(uint32_t* r, uint32_t addr) {
    asm volatile("ldmatrix.sync.aligned.m8n8.x4.shared.b16 {%0,%1,%2,%3}, [%4];"
                 : "=r"(r[0]), "=r"(r[1]), "=r"(r[2]), "=r"(r[3]) : "r"(addr));
}
__device__ __forceinline__ void ldsm4t(uint32_t* r, uint32_t addr) {
    asm volatile("ldmatrix.sync.aligned.m8n8.x4.trans.shared.b16 {%0,%1,%2,%3}, [%4];"
                 : "=r"(r[0]), "=r"(r[1]), "=r"(r[2]), "=r"(r[3]) : "r"(addr));
}
__device__ __forceinline__ void mma16816(float* c, const uint32_t* a, const uint32_t* b) {
    asm volatile(
        "mma.sync.aligned.m16n8k16.row.col.f32.f16.f16.f32 "
        "{%0,%1,%2,%3}, {%4,%5,%6,%7}, {%8,%9}, {%0,%1,%2,%3};"
        : "+f"(c[0]), "+f"(c[1]), "+f"(c[2]), "+f"(c[3])
        : "r"(a[0]), "r"(a[1]), "r"(a[2]), "r"(a[3]), "r"(b[0]), "r"(b[1]));
}

// ============================================================
// fp32 -> fp16 convert
// ============================================================
__global__ void to_half(const float* __restrict__ x, __half* __restrict__ y, int n4) {
    int i = blockIdx.x * blockDim.x + threadIdx.x;
    if (i >= n4) return;
    float4 v = ((const float4*)x)[i];
    __half2* Y = (__half2*)y;
    Y[2 * i]     = __floats2half2_rn(v.x, v.y);
    Y[2 * i + 1] = __floats2half2_rn(v.z, v.w);
}

// ============================================================
// fp16 mma.sync GEMM: C[m,n] = sum_k A[m,k]*B[n,k], K=2048, fp32 out.
// CTA 128x128x32, 256 threads (8 warps 2m x 4n), warp tile 64x32.
// 4-stage cp.async pipeline, XOR-swizzled smem.
// ============================================================
#define BM 128
#define BN 128
#define BK 32
#define NIT (KTOT / BK)          // 64
#define TILEB (BM * 64)          // 8KB per operand tile (128 rows * 32 fp16)
#define STAGEB (2 * TILEB)       // A + B = 16KB
#define NSTAGE 4
#define GSMEM (NSTAGE * STAGEB)  // 64KB

__device__ __forceinline__ uint32_t swz(int row, int ci) {
    return (uint32_t)(row * 64 + ((ci ^ ((row >> 1) & 3)) << 4));
}

__global__ __launch_bounds__(256)
void gemm_mma(const __half* __restrict__ A, const __half* __restrict__ B,
              float* __restrict__ C, int N) {
    extern __shared__ char smem[];
    const uint32_t sb = smem_u32(smem);
    const int tid = threadIdx.x;
    const int lane = tid & 31;
    const int w = tid >> 5;
    const int wm = w & 1;
    const int wn = w >> 1;
    const int m0 = blockIdx.y * BM;
    const int n0 = blockIdx.x * BN;

    const int arow_l = (lane & 7) + ((lane >> 3) & 1) * 8;
    const int ahi_c  = lane >> 4;
    const int brow_l = (lane & 7) + ((lane >> 4) & 1) * 8;
    const int bhi_c  = (lane >> 3) & 1;
    uint32_t aoff[4], boff[2];
#pragma unroll
    for (int mi = 0; mi < 4; mi++) aoff[mi] = swz(wm * 64 + mi * 16 + arow_l, ahi_c);
#pragma unroll
    for (int nt = 0; nt < 2; nt++) boff[nt] = TILEB + swz(wn * 32 + nt * 16 + brow_l, bhi_c);

    const int grow = tid >> 2;
    const int gci  = tid & 3;

    float acc[4][4][4];
#pragma unroll
    for (int mi = 0; mi < 4; mi++)
#pragma unroll
        for (int ni = 0; ni < 4; ni++)
#pragma unroll
            for (int e = 0; e < 4; e++) acc[mi][ni][e] = 0.f;

    auto load_stage = [&](int it, int buf) {
        const int k0 = it * BK;
        const uint32_t st = sb + buf * STAGEB;
#pragma unroll
        for (int p = 0; p < 2; p++) {
            int row = grow + p * 64;
            uint32_t so = swz(row, gci);
            cpasync16(st + so,         A + (size_t)(m0 + row) * KTOT + k0 + gci * 8);
            cpasync16(st + TILEB + so, B + (size_t)(n0 + row) * KTOT + k0 + gci * 8);
        }
    };

#pragma unroll
    for (int p = 0; p < 3; p++) {
        load_stage(p, p);
        asm volatile("cp.async.commit_group;" ::: "memory");
    }

    for (int it = 0; it < NIT; it++) {
        asm volatile("cp.async.wait_group 2;" ::: "memory");
        __syncthreads();

        const uint32_t st = sb + (it & 3) * STAGEB;
#pragma unroll
        for (int kc = 0; kc < 2; kc++) {
            const uint32_t kx = kc << 5;
            uint32_t ah[4][4], bh[4][2];
#pragma unroll
            for (int mi = 0; mi < 4; mi++) ldsm4(ah[mi], st + (aoff[mi] ^ kx));
#pragma unroll
            for (int nt = 0; nt < 2; nt++) {
                uint32_t t[4];
                ldsm4(t, st + (boff[nt] ^ kx));
                bh[2 * nt][0] = t[0]; bh[2 * nt][1] = t[1];
                bh[2 * nt + 1][0] = t[2]; bh[2 * nt + 1][1] = t[3];
            }
#pragma unroll
            for (int mi = 0; mi < 4; mi++)
#pragma unroll
                for (int ni = 0; ni < 4; ni++)
                    mma16816(acc[mi][ni], ah[mi], bh[ni]);
        }
        __syncthreads();

        if (it + 3 < NIT) load_stage(it + 3, (it + 3) & 3);
        asm volatile("cp.async.commit_group;" ::: "memory");
    }

    const int mrow = m0 + wm * 64 + (lane >> 2);
    const int ncol = n0 + wn * 32 + (lane & 3) * 2;
#pragma unroll
    for (int mi = 0; mi < 4; mi++)
#pragma unroll
        for (int ni = 0; ni < 4; ni++) {
            float* c0 = C + (size_t)(mrow + mi * 16) * N + ncol + ni * 8;
            float* c1 = C + (size_t)(mrow + mi * 16 + 8) * N + ncol + ni * 8;
            *(float2*)c0 = make_float2(acc[mi][ni][0], acc[mi][ni][1]);
            *(float2*)c1 = make_float2(acc[mi][ni][2], acc[mi][ni][3]);
        }
}

// ============================================================
// RoPE + RMS-norm, fp32 in -> fp16 out (optionally pre-scaled).
// ============================================================
__global__ void rope_rms_h(const float* __restrict__ X, const float* __restrict__ w,
                           const int* __restrict__ pos_ids, int rowstride,
                           float oscale, __half* __restrict__ Y) {
    const int s = blockIdx.x;
    const int h = blockIdx.y;
    const int d = threadIdx.x;            // 0..63 (pair d, d+64)
    const float* x = X + (size_t)s * rowstride + h * HD;

    float pos = (float)pos_ids[s];
    const float NL2T_64 = 19.931568569324174f / 64.0f;
    float inv = exp2f(-(float)d * NL2T_64);
    float f = pos * inv;
    float sn, c;
    sincosf(f, &sn, &c);

    float x1 = x[d], x2 = x[d + 64];
    float o1 = x1 * c - x2 * sn;
    float o2 = x2 * c + x1 * sn;

    float sq = o1 * o1 + o2 * o2;
#pragma unroll
    for (int off = 16; off; off >>= 1) sq += __shfl_xor_sync(0xffffffffu, sq, off);
    __shared__ float wsum[2];
    if ((threadIdx.x & 31) == 0) wsum[threadIdx.x >> 5] = sq;
    __syncthreads();
    float var = (wsum[0] + wsum[1]) * (1.0f / 128.0f);
    float r = rsqrtf(var + 1e-6f) * oscale;

    __half* y = Y + (size_t)s * rowstride + h * HD;
    y[d]      = __float2half_rn(o1 * r * w[d]);
    y[d + 64] = __float2half_rn(o2 * r * w[d + 64]);
}

// ============================================================
// fp16 tensor-core causal GQA flash attention.
// CTA: 4 warps, q-tile 64 (16 rows/warp), kv-tile 64.
// Writes fp16 ctx directly.
// ============================================================
#define AQT 64
#define AKT 64
#define ASM_Q 0
#define ASM_K 16384
#define ASM_V 32768
#define ASM_TOT 49152

__device__ __forceinline__ uint32_t aswz(int row, int c) {
    return (uint32_t)(row * 256 + ((c ^ (row & 7)) << 4));
}

__global__ __launch_bounds__(128)
void attn_mma(const __half* __restrict__ Qh, const __half* __restrict__ Kh,
              const __half* __restrict__ Vh, __half* __restrict__ Ch) {
    extern __shared__ char sm[];
    const uint32_t sb = smem_u32(sm);
    const int qt = (gridDim.x - 1) - blockIdx.x;    // heavy tiles first
    const int h  = blockIdx.y;
    const int kh = h >> 1;
    const int tid = threadIdx.x;
    const int lane = tid & 31;
    const int w = tid >> 5;
    const int q0 = qt * AQT;

    // load Q tile (64 x 128 fp16, swizzled)
#pragma unroll
    for (int i = 0; i < 8; i++) {
        int idx = tid + i * 128;
        int row = idx >> 4;
        int c   = idx & 15;
        cpasync16(sb + ASM_Q + aswz(row, c),
                  Qh + (size_t)(q0 + row) * QDIM + h * HD + c * 8);
    }
    asm volatile("cp.async.commit_group;" ::: "memory");

    float O[16][4];
#pragma unroll
    for (int nt = 0; nt < 16; nt++)
#pragma unroll
        for (int e = 0; e < 4; e++) O[nt][e] = 0.f;
    float m0 = -1e30f, m1 = -1e30f, lp0 = 0.f, lp1 = 0.f;

    const int arow = (lane & 7) + ((lane >> 3) & 1) * 8;   // a-frag row-in-16
    const int ac   = lane >> 4;
    const int brow = (lane & 7) + ((lane >> 4) & 1) * 8;   // b-frag (non-trans) row-in-16
    const int bc   = (lane >> 3) & 1;
    const int vrow = (lane & 7) + ((lane >> 3) & 1) * 8;   // trans b-frag row-in-16
    const int vc   = lane >> 4;                            // trans b-frag col group
    const int r0   = lane >> 2;

    for (int t = 0; t <= qt; t++) {
        const int k0 = t * AKT;
#pragma unroll
        for (int i = 0; i < 8; i++) {
            int idx = tid + i * 128;
            int row = idx >> 4;
            int c   = idx & 15;
            cpasync16(sb + ASM_K + aswz(row, c),
                      Kh + (size_t)(k0 + row) * KVDIM + kh * HD + c * 8);
            cpasync16(sb + ASM_V + aswz(row, c),
                      Vh + (size_t)(k0 + row) * KVDIM + kh * HD + c * 8);
        }
        asm volatile("cp.async.commit_group;" ::: "memory");
        asm volatile("cp.async.wait_group 0;" ::: "memory");
        __syncthreads();

        // scores S[16 x 64] for this warp
        float Sx[8][4];
#pragma unroll
        for (int nn = 0; nn < 8; nn++)
#pragma unroll
            for (int e = 0; e < 4; e++) Sx[nn][e] = 0.f;

#pragma unroll
        for (int kk = 0; kk < 8; kk++) {
            uint32_t a[4];
            ldsm4(a, sb + ASM_Q + aswz(16 * w + arow, kk * 2 + ac));
#pragma unroll
            for (int nt = 0; nt < 4; nt++) {
                uint32_t b[4];
                ldsm4(b, sb + ASM_K + aswz(nt * 16 + brow, kk * 2 + bc));
                mma16816(Sx[2 * nt],     a, b);
                mma16816(Sx[2 * nt + 1], a, b + 2);
            }
        }

        if (t == qt) {   // diagonal tile: mask col > row
#pragma unroll
            for (int nn = 0; nn < 8; nn++)
#pragma unroll
                for (int e = 0; e < 4; e++) {
                    int col = nn * 8 + (lane & 3) * 2 + (e & 1);
                    int row = 16 * w + r0 + 8 * (e >> 1);
                    if (col > row) Sx[nn][e] = -1e30f;
                }
        }

        // online softmax (rows r0 and r0+8)
        float t0 = -1e30f, t1 = -1e30f;
#pragma unroll
        for (int nn = 0; nn < 8; nn++) {
            t0 = fmaxf(t0, fmaxf(Sx[nn][0], Sx[nn][1]));
            t1 = fmaxf(t1, fmaxf(Sx[nn][2], Sx[nn][3]));
        }
        t0 = fmaxf(t0, __shfl_xor_sync(0xffffffffu, t0, 1));
        t0 = fmaxf(t0, __shfl_xor_sync(0xffffffffu, t0, 2));
        t1 = fmaxf(t1, __shfl_xor_sync(0xffffffffu, t1, 1));
        t1 = fmaxf(t1, __shfl_xor_sync(0xffffffffu, t1, 2));
        float n0 = fmaxf(m0, t0), n1 = fmaxf(m1, t1);
        float a0 = __expf(m0 - n0), a1 = __expf(m1 - n1);
        m0 = n0; m1 = n1; lp0 *= a0; lp1 *= a1;
#pragma unroll
        for (int nt = 0; nt < 16; nt++) {
            O[nt][0] *= a0; O[nt][1] *= a0; O[nt][2] *= a1; O[nt][3] *= a1;
        }

        uint32_t pa[4][4];
#pragma unroll
        for (int j = 0; j < 4; j++) {
            float p00 = __expf(Sx[2 * j][0] - n0),     p01 = __expf(Sx[2 * j][1] - n0);
            float p02 = __expf(Sx[2 * j][2] - n1),     p03 = __expf(Sx[2 * j][3] - n1);
            float p10 = __expf(Sx[2 * j + 1][0] - n0), p11 = __expf(Sx[2 * j + 1][1] - n0);
            float p12 = __expf(Sx[2 * j + 1][2] - n1), p13 = __expf(Sx[2 * j + 1][3] - n1);
            lp0 += p00 + p01 + p10 + p11;
            lp1 += p02 + p03 + p12 + p13;
            pa[j][0] = h2u(__floats2half2_rn(p00, p01));
            pa[j][1] = h2u(__floats2half2_rn(p02, p03));
            pa[j][2] = h2u(__floats2half2_rn(p10, p11));
            pa[j][3] = h2u(__floats2half2_rn(p12, p13));
        }

        // O += P @ V   (V via ldmatrix.trans)
#pragma unroll
        for (int j = 0; j < 4; j++) {
#pragma unroll
            for (int g = 0; g < 8; g++) {
                uint32_t b[4];
                ldsm4t(b, sb + ASM_V + aswz(j * 16 + vrow, g * 2 + vc));
                mma16816(O[2 * g],     pa[j], b);
                mma16816(O[2 * g + 1], pa[j], b + 2);
            }
        }
        __syncthreads();
    }

    lp0 += __shfl_xor_sync(0xffffffffu, lp0, 1);
    lp0 += __shfl_xor_sync(0xffffffffu, lp0, 2);
    lp1 += __shfl_xor_sync(0xffffffffu, lp1, 1);
    lp1 += __shfl_xor_sync(0xffffffffu, lp1, 2);
    float rl0 = 1.0f / lp0, rl1 = 1.0f / lp1;

    const int ro0 = q0 + 16 * w + r0;
    const int ro1 = ro0 + 8;
    const int colb = (lane & 3) * 2;
    __half2* C2 = (__half2*)Ch;
#pragma unroll
    for (int nt = 0; nt < 16; nt++) {
        int col = nt * 8 + colb;
        C2[((size_t)ro0 * QDIM + h * HD + col) >> 1] = __floats2half2_rn(O[nt][0] * rl0, O[nt][1] * rl0);
        C2[((size_t)ro1 * QDIM + h * HD + col) >> 1] = __floats2half2_rn(O[nt][2] * rl1, O[nt][3] * rl1);
    }
}

// ============================================================
// launch
// ============================================================
extern "C" void kernel_launch(void* const* d_in, const int* in_sizes, int n_in,
                              void* d_out, int out_size) {
    const float* X   = (const float*)d_in[0];
    const int*   pos = (const int*)d_in[2];
    const float* wq  = (const float*)d_in[3];
    const float* wk  = (const float*)d_in[4];
    const float* wv  = (const float*)d_in[5];
    const float* wo  = (const float*)d_in[6];
    const float* qnw = (const float*)d_in[7];
    const float* knw = (const float*)d_in[8];
    float* out = (float*)d_out;

    float *Q, *Kb, *Vb;
    cudaGetSymbolAddress((void**)&Q,  g_Q);
    cudaGetSymbolAddress((void**)&Kb, g_K);
    cudaGetSymbolAddress((void**)&Vb, g_V);

    __half *Xh, *Wqh, *Wkh, *Wvh, *Woh, *Qh, *Kh, *Vh, *Ch;
    cudaGetSymbolAddress((void**)&Xh,  g_Xh);
    cudaGetSymbolAddress((void**)&Wqh, g_Wqh);
    cudaGetSymbolAddress((void**)&Wkh, g_Wkh);
    cudaGetSymbolAddress((void**)&Wvh, g_Wvh);
    cudaGetSymbolAddress((void**)&Woh, g_Woh);
    cudaGetSymbolAddress((void**)&Qh,  g_Qh);
    cudaGetSymbolAddress((void**)&Kh,  g_Kh);
    cudaGetSymbolAddress((void**)&Vh,  g_Vh);
    cudaGetSymbolAddress((void**)&Ch,  g_Ch);

    cudaFuncSetAttribute(gemm_mma, cudaFuncAttributeMaxDynamicSharedMemorySize, GSMEM);
    cudaFuncSetAttribute(attn_mma, cudaFuncAttributeMaxDynamicSharedMemorySize, ASM_TOT);

    const int T = 256;
    to_half<<<(S * HID / 4 + T - 1) / T, T>>>(X,  Xh,  S * HID / 4);
    to_half<<<(QDIM * HID / 4 + T - 1) / T, T>>>(wq, Wqh, QDIM * HID / 4);
    to_half<<<(KVDIM * HID / 4 + T - 1) / T, T>>>(wk, Wkh, KVDIM * HID / 4);
    to_half<<<(KVDIM * HID / 4 + T - 1) / T, T>>>(wv, Wvh, KVDIM * HID / 4);
    to_half<<<(HID * QDIM / 4 + T - 1) / T, T>>>(wo, Woh, HID * QDIM / 4);

    gemm_mma<<<dim3(QDIM / BN,  S / BM), 256, GSMEM>>>(Xh, Wqh, Q,  QDIM);
    gemm_mma<<<dim3(KVDIM / BN, S / BM), 256, GSMEM>>>(Xh, Wkh, Kb, KVDIM);
    gemm_mma<<<dim3(KVDIM / BN, S / BM), 256, GSMEM>>>(Xh, Wvh, Vb, KVDIM);

    const float scale = 0.08838834764831845f;   // 1/sqrt(128)
    rope_rms_h<<<dim3(S, NH),  64>>>(Q,  qnw, pos, QDIM,  scale, Qh);
    rope_rms_h<<<dim3(S, NKV), 64>>>(Kb, knw, pos, KVDIM, 1.0f,  Kh);
    to_half<<<(S * KVDIM / 4 + T - 1) / T, T>>>(Vb, Vh, S * KVDIM / 4);

    attn_mma<<<dim3(S / AQT, NH), 128, ASM_TOT>>>(Qh, Kh, Vh, Ch);

    gemm_mma<<<dim3(QDIM / BN, S / BM), 256, GSMEM>>>(Ch, Woh, out, QDIM);
}

// round 10
// speedup vs baseline: 8.7654x; 1.0823x over previous
#include <cuda_runtime.h>
#include <cuda_fp16.h>
#include <cstdint>
#include <math.h>

// ---------------- problem constants ----------------
#define S       2048
#define HID     2048
#define NH      16
#define NKV     8
#define HD      128
#define QDIM    (NH*HD)    // 2048
#define KVDIM   (NKV*HD)   // 1024
#define KTOT    2048
#define NQKV    (QDIM + 2*KVDIM)   // 4096

// ---------------- scratch (no cudaMalloc allowed) ----------------
__device__ float  g_Q[S * QDIM];
__device__ float  g_K[S * KVDIM];
__device__ float2 g_cs[S * 64];

__device__ __half g_Xh[S * HID];
__device__ __half g_Wqkvh[NQKV * HID];      // Wq rows 0..2047, Wk 2048..3071, Wv 3072..4095
__device__ __half g_Woh[HID * QDIM];
__device__ __half g_Qh[S * QDIM];
__device__ __half g_Kh[S * KVDIM];
__device__ __half g_Vh[S * KVDIM];
__device__ __half g_Ch[S * QDIM];

// ================= PTX helpers (sm_80-era, valid on base sm_103) =================
__device__ __forceinline__ uint32_t smem_u32(const void* p) {
    uint32_t a;
    asm("{ .reg .u64 t; cvta.to.shared.u64 t, %1; cvt.u32.u64 %0, t; }" : "=r"(a) : "l"(p));
    return a;
}
__device__ __forceinline__ uint32_t h2u(__half2 h) {
    return *reinterpret_cast<uint32_t*>(&h);
}
__device__ __forceinline__ void cpasync16(uint32_t s, const void* g) {
    asm volatile("cp.async.cg.shared.global [%0], [%1], 16;" :: "r"(s), "l"(g));
}
__device__ __forceinline__ void ldsm4(uint32_t* r, uint32_t addr) {
    asm volatile("ldmatrix.sync.aligned.m8n8.x4.shared.b16 {%0,%1,%2,%3}, [%4];"
                 : "=r"(r[0]), "=r"(r[1]), "=r"(r[2]), "=r"(r[3]) : "r"(addr));
}
__device__ __forceinline__ void ldsm4t(uint32_t* r, uint32_t addr) {
    asm volatile("ldmatrix.sync.aligned.m8n8.x4.trans.shared.b16 {%0,%1,%2,%3}, [%4];"
                 : "=r"(r[0]), "=r"(r[1]), "=r"(r[2]), "=r"(r[3]) : "r"(addr));
}
__device__ __forceinline__ void mma16816(float* c, const uint32_t* a, const uint32_t* b) {
    asm volatile(
        "mma.sync.aligned.m16n8k16.row.col.f32.f16.f16.f32 "
        "{%0,%1,%2,%3}, {%4,%5,%6,%7}, {%8,%9}, {%0,%1,%2,%3};"
        : "+f"(c[0]), "+f"(c[1]), "+f"(c[2]), "+f"(c[3])
        : "r"(a[0]), "r"(a[1]), "r"(a[2]), "r"(a[3]), "r"(b[0]), "r"(b[1]));
}

// ============================================================
// fp32 -> fp16 convert
// ============================================================
__global__ void to_half(const float* __restrict__ x, __half* __restrict__ y, int n4) {
    int i = blockIdx.x * blockDim.x + threadIdx.x;
    if (i >= n4) return;
    float4 v = ((const float4*)x)[i];
    __half2* Y = (__half2*)y;
    Y[2 * i]     = __floats2half2_rn(v.x, v.y);
    Y[2 * i + 1] = __floats2half2_rn(v.z, v.w);
}

// ============================================================
// RoPE cos/sin table: one entry per (seq pos, freq idx 0..63)
// ============================================================
__global__ void cs_table(const int* __restrict__ pos_ids, float2* __restrict__ cs) {
    const int s = blockIdx.x;
    const int d = threadIdx.x;
    float pos = (float)pos_ids[s];
    const float NL2T_64 = 19.931568569324174f / 64.0f;
    float inv = exp2f(-(float)d * NL2T_64);
    float sn, c;
    sincosf(pos * inv, &sn, &c);
    cs[s * 64 + d] = make_float2(c, sn);
}

// ============================================================
// fp16 mma.sync GEMM mainloop pieces (shared between kernels)
// CTA 128x128x32, 256 threads (8 warps 2m x 4n), warp tile 64x32.
// ============================================================
#define BM 128
#define BN 128
#define BK 32
#define NIT (KTOT / BK)          // 64
#define TILEB (BM * 64)          // 8KB per operand tile
#define STAGEB (2 * TILEB)       // A + B = 16KB
#define NSTAGE 4
#define GSMEM (NSTAGE * STAGEB)  // 64KB

__device__ __forceinline__ uint32_t swz(int row, int ci) {
    return (uint32_t)(row * 64 + ((ci ^ ((row >> 1) & 3)) << 4));
}

// mainloop producing acc[4][4][4]; A rows at m0, B rows at bn0 (within Bsrc)
template <typename EpiF>
__device__ __forceinline__ void gemm_core(const __half* __restrict__ A,
                                          const __half* __restrict__ B,
                                          int m0, int bn0, char* smem, EpiF epi) {
    const uint32_t sb = smem_u32(smem);
    const int tid = threadIdx.x;
    const int lane = tid & 31;
    const int w = tid >> 5;
    const int wm = w & 1;
    const int wn = w >> 1;

    const int arow_l = (lane & 7) + ((lane >> 3) & 1) * 8;
    const int ahi_c  = lane >> 4;
    const int brow_l = (lane & 7) + ((lane >> 4) & 1) * 8;
    const int bhi_c  = (lane >> 3) & 1;
    uint32_t aoff[4], boff[2];
#pragma unroll
    for (int mi = 0; mi < 4; mi++) aoff[mi] = swz(wm * 64 + mi * 16 + arow_l, ahi_c);
#pragma unroll
    for (int nt = 0; nt < 2; nt++) boff[nt] = TILEB + swz(wn * 32 + nt * 16 + brow_l, bhi_c);

    const int grow = tid >> 2;
    const int gci  = tid & 3;

    float acc[4][4][4];
#pragma unroll
    for (int mi = 0; mi < 4; mi++)
#pragma unroll
        for (int ni = 0; ni < 4; ni++)
#pragma unroll
            for (int e = 0; e < 4; e++) acc[mi][ni][e] = 0.f;

    auto load_stage = [&](int it, int buf) {
        const int k0 = it * BK;
        const uint32_t st = sb + buf * STAGEB;
#pragma unroll
        for (int p = 0; p < 2; p++) {
            int row = grow + p * 64;
            uint32_t so = swz(row, gci);
            cpasync16(st + so,         A + (size_t)(m0 + row) * KTOT + k0 + gci * 8);
            cpasync16(st + TILEB + so, B + (size_t)(bn0 + row) * KTOT + k0 + gci * 8);
        }
    };

#pragma unroll
    for (int p = 0; p < 3; p++) {
        load_stage(p, p);
        asm volatile("cp.async.commit_group;" ::: "memory");
    }

    for (int it = 0; it < NIT; it++) {
        asm volatile("cp.async.wait_group 2;" ::: "memory");
        __syncthreads();

        const uint32_t st = sb + (it & 3) * STAGEB;
#pragma unroll
        for (int kc = 0; kc < 2; kc++) {
            const uint32_t kx = kc << 5;
            uint32_t ah[4][4], bh[4][2];
#pragma unroll
            for (int mi = 0; mi < 4; mi++) ldsm4(ah[mi], st + (aoff[mi] ^ kx));
#pragma unroll
            for (int nt = 0; nt < 2; nt++) {
                uint32_t t[4];
                ldsm4(t, st + (boff[nt] ^ kx));
                bh[2 * nt][0] = t[0]; bh[2 * nt][1] = t[1];
                bh[2 * nt + 1][0] = t[2]; bh[2 * nt + 1][1] = t[3];
            }
#pragma unroll
            for (int mi = 0; mi < 4; mi++)
#pragma unroll
                for (int ni = 0; ni < 4; ni++)
                    mma16816(acc[mi][ni], ah[mi], bh[ni]);
        }
        __syncthreads();

        if (it + 3 < NIT) load_stage(it + 3, (it + 3) & 3);
        asm volatile("cp.async.commit_group;" ::: "memory");
    }

    // hand accumulators to epilogue: local row/col of warp fragment
    const int lrow = wm * 64 + (lane >> 2);      // + mi*16 (+8)
    const int lcol = wn * 32 + (lane & 3) * 2;   // + ni*8
    epi(acc, lrow, lcol);
}

// ---- fused QKV projection: C segments Q(fp32), K(fp32), V(fp16) ----
__global__ __launch_bounds__(256)
void gemm_qkv(const __half* __restrict__ Xh, const __half* __restrict__ Wqkv,
              float* __restrict__ Q, float* __restrict__ K, __half* __restrict__ Vh) {
    extern __shared__ char smem[];
    const int m0 = blockIdx.y * BM;
    const int n0 = blockIdx.x * BN;   // 0..4095

    if (n0 < QDIM) {
        gemm_core(Xh, Wqkv, m0, n0, smem, [&](float a[4][4][4], int lr, int lc) {
#pragma unroll
            for (int mi = 0; mi < 4; mi++)
#pragma unroll
                for (int ni = 0; ni < 4; ni++) {
                    float* c0 = Q + (size_t)(m0 + lr + mi * 16) * QDIM + n0 + lc + ni * 8;
                    float* c1 = c0 + 8 * QDIM;
                    *(float2*)c0 = make_float2(a[mi][ni][0], a[mi][ni][1]);
                    *(float2*)c1 = make_float2(a[mi][ni][2], a[mi][ni][3]);
                }
        });
    } else if (n0 < QDIM + KVDIM) {
        const int kn0 = n0 - QDIM;
        gemm_core(Xh, Wqkv, m0, n0, smem, [&](float a[4][4][4], int lr, int lc) {
#pragma unroll
            for (int mi = 0; mi < 4; mi++)
#pragma unroll
                for (int ni = 0; ni < 4; ni++) {
                    float* c0 = K + (size_t)(m0 + lr + mi * 16) * KVDIM + kn0 + lc + ni * 8;
                    float* c1 = c0 + 8 * KVDIM;
                    *(float2*)c0 = make_float2(a[mi][ni][0], a[mi][ni][1]);
                    *(float2*)c1 = make_float2(a[mi][ni][2], a[mi][ni][3]);
                }
        });
    } else {
        const int vn0 = n0 - QDIM - KVDIM;
        gemm_core(Xh, Wqkv, m0, n0, smem, [&](float a[4][4][4], int lr, int lc) {
#pragma unroll
            for (int mi = 0; mi < 4; mi++)
#pragma unroll
                for (int ni = 0; ni < 4; ni++) {
                    __half2* c0 = (__half2*)(Vh + (size_t)(m0 + lr + mi * 16) * KVDIM + vn0 + lc + ni * 8);
                    __half2* c1 = (__half2*)((__half*)c0 + 8 * KVDIM);
                    *c0 = __floats2half2_rn(a[mi][ni][0], a[mi][ni][1]);
                    *c1 = __floats2half2_rn(a[mi][ni][2], a[mi][ni][3]);
                }
        });
    }
}

// ---- output projection: fp32 out ----
__global__ __launch_bounds__(256)
void gemm_out(const __half* __restrict__ A, const __half* __restrict__ B,
              float* __restrict__ C) {
    extern __shared__ char smem[];
    const int m0 = blockIdx.y * BM;
    const int n0 = blockIdx.x * BN;
    gemm_core(A, B, m0, n0, smem, [&](float a[4][4][4], int lr, int lc) {
#pragma unroll
        for (int mi = 0; mi < 4; mi++)
#pragma unroll
            for (int ni = 0; ni < 4; ni++) {
                float* c0 = C + (size_t)(m0 + lr + mi * 16) * QDIM + n0 + lc + ni * 8;
                float* c1 = c0 + 8 * QDIM;
                *(float2*)c0 = make_float2(a[mi][ni][0], a[mi][ni][1]);
                *(float2*)c1 = make_float2(a[mi][ni][2], a[mi][ni][3]);
            }
    });
}

// ============================================================
// RoPE + RMS-norm (table-driven), fp32 in -> fp16 out (pre-scaled).
// ============================================================
__global__ void rope_rms_h(const float* __restrict__ X, const float* __restrict__ w,
                           const float2* __restrict__ CS, int rowstride,
                           float oscale, __half* __restrict__ Y) {
    const int s = blockIdx.x;
    const int h = blockIdx.y;
    const int d = threadIdx.x;            // 0..63 (pair d, d+64)
    const float* x = X + (size_t)s * rowstride + h * HD;

    float2 cs = CS[s * 64 + d];
    float x1 = x[d], x2 = x[d + 64];
    float o1 = x1 * cs.x - x2 * cs.y;
    float o2 = x2 * cs.x + x1 * cs.y;

    float sq = o1 * o1 + o2 * o2;
#pragma unroll
    for (int off = 16; off; off >>= 1) sq += __shfl_xor_sync(0xffffffffu, sq, off);
    __shared__ float wsum[2];
    if ((threadIdx.x & 31) == 0) wsum[threadIdx.x >> 5] = sq;
    __syncthreads();
    float var = (wsum[0] + wsum[1]) * (1.0f / 128.0f);
    float r = rsqrtf(var + 1e-6f) * oscale;

    __half* y = Y + (size_t)s * rowstride + h * HD;
    y[d]      = __float2half_rn(o1 * r * w[d]);
    y[d + 64] = __float2half_rn(o2 * r * w[d + 64]);
}

// ============================================================
// fp16 tensor-core causal GQA flash attention, double-buffered K/V.
// CTA: 4 warps, q-tile 64, kv-tile 64.
// ============================================================
#define AQT 64
#define AKT 64
#define ASM_Q 0
#define ASM_KV0 16384            // buf0: K@16K, V@32K; buf1: K@48K, V@64K
#define ASM_TOT 81920

__device__ __forceinline__ uint32_t aswz(int row, int c) {
    return (uint32_t)(row * 256 + ((c ^ (row & 7)) << 4));
}

__global__ __launch_bounds__(128)
void attn_mma(const __half* __restrict__ Qh, const __half* __restrict__ Kh,
              const __half* __restrict__ Vh, __half* __restrict__ Ch) {
    extern __shared__ char sm[];
    const uint32_t sb = smem_u32(sm);
    const int qt = (gridDim.x - 1) - blockIdx.x;    // heavy tiles first
    const int h  = blockIdx.y;
    const int kh = h >> 1;
    const int tid = threadIdx.x;
    const int lane = tid & 31;
    const int w = tid >> 5;
    const int q0 = qt * AQT;

    auto load_kv = [&](int t, int buf) {
        const int k0 = t * AKT;
        const uint32_t kb = sb + ASM_KV0 + buf * 32768;
#pragma unroll
        for (int i = 0; i < 8; i++) {
            int idx = tid + i * 128;
            int row = idx >> 4;
            int c   = idx & 15;
            cpasync16(kb + aswz(row, c),
                      Kh + (size_t)(k0 + row) * KVDIM + kh * HD + c * 8);
            cpasync16(kb + 16384 + aswz(row, c),
                      Vh + (size_t)(k0 + row) * KVDIM + kh * HD + c * 8);
        }
        asm volatile("cp.async.commit_group;" ::: "memory");
    };

    // load Q tile (64 x 128 fp16, swizzled)
#pragma unroll
    for (int i = 0; i < 8; i++) {
        int idx = tid + i * 128;
        int row = idx >> 4;
        int c   = idx & 15;
        cpasync16(sb + ASM_Q + aswz(row, c),
                  Qh + (size_t)(q0 + row) * QDIM + h * HD + c * 8);
    }
    asm volatile("cp.async.commit_group;" ::: "memory");
    load_kv(0, 0);

    float O[16][4];
#pragma unroll
    for (int nt = 0; nt < 16; nt++)
#pragma unroll
        for (int e = 0; e < 4; e++) O[nt][e] = 0.f;
    float m0 = -1e30f, m1 = -1e30f, lp0 = 0.f, lp1 = 0.f;

    const int arow = (lane & 7) + ((lane >> 3) & 1) * 8;
    const int ac   = lane >> 4;
    const int brow = (lane & 7) + ((lane >> 4) & 1) * 8;
    const int bc   = (lane >> 3) & 1;
    const int vrow = (lane & 7) + ((lane >> 3) & 1) * 8;
    const int vc   = lane >> 4;
    const int r0   = lane >> 2;

    for (int t = 0; t <= qt; t++) {
        const int buf = t & 1;
        if (t < qt) {
            load_kv(t + 1, buf ^ 1);
            asm volatile("cp.async.wait_group 1;" ::: "memory");
        } else {
            asm volatile("cp.async.wait_group 0;" ::: "memory");
        }
        __syncthreads();
        const uint32_t kB = sb + ASM_KV0 + buf * 32768;
        const uint32_t vB = kB + 16384;

        // scores S[16 x 64] for this warp
        float Sx[8][4];
#pragma unroll
        for (int nn = 0; nn < 8; nn++)
#pragma unroll
            for (int e = 0; e < 4; e++) Sx[nn][e] = 0.f;

#pragma unroll
        for (int kk = 0; kk < 8; kk++) {
            uint32_t a[4];
            ldsm4(a, sb + ASM_Q + aswz(16 * w + arow, kk * 2 + ac));
#pragma unroll
            for (int nt = 0; nt < 4; nt++) {
                uint32_t b[4];
                ldsm4(b, kB + aswz(nt * 16 + brow, kk * 2 + bc));
                mma16816(Sx[2 * nt],     a, b);
                mma16816(Sx[2 * nt + 1], a, b + 2);
            }
        }

        if (t == qt) {   // diagonal tile: mask col > row
#pragma unroll
            for (int nn = 0; nn < 8; nn++)
#pragma unroll
                for (int e = 0; e < 4; e++) {
                    int col = nn * 8 + (lane & 3) * 2 + (e & 1);
                    int row = 16 * w + r0 + 8 * (e >> 1);
                    if (col > row) Sx[nn][e] = -1e30f;
                }
        }

        // online softmax (rows r0 and r0+8)
        float t0 = -1e30f, t1 = -1e30f;
#pragma unroll
        for (int nn = 0; nn < 8; nn++) {
            t0 = fmaxf(t0, fmaxf(Sx[nn][0], Sx[nn][1]));
            t1 = fmaxf(t1, fmaxf(Sx[nn][2], Sx[nn][3]));
        }
        t0 = fmaxf(t0, __shfl_xor_sync(0xffffffffu, t0, 1));
        t0 = fmaxf(t0, __shfl_xor_sync(0xffffffffu, t0, 2));
        t1 = fmaxf(t1, __shfl_xor_sync(0xffffffffu, t1, 1));
        t1 = fmaxf(t1, __shfl_xor_sync(0xffffffffu, t1, 2));
        float n0 = fmaxf(m0, t0), n1 = fmaxf(m1, t1);
        float a0 = __expf(m0 - n0), a1 = __expf(m1 - n1);
        m0 = n0; m1 = n1; lp0 *= a0; lp1 *= a1;
#pragma unroll
        for (int nt = 0; nt < 16; nt++) {
            O[nt][0] *= a0; O[nt][1] *= a0; O[nt][2] *= a1; O[nt][3] *= a1;
        }

        uint32_t pa[4][4];
#pragma unroll
        for (int j = 0; j < 4; j++) {
            float p00 = __expf(Sx[2 * j][0] - n0),     p01 = __expf(Sx[2 * j][1] - n0);
            float p02 = __expf(Sx[2 * j][2] - n1),     p03 = __expf(Sx[2 * j][3] - n1);
            float p10 = __expf(Sx[2 * j + 1][0] - n0), p11 = __expf(Sx[2 * j + 1][1] - n0);
            float p12 = __expf(Sx[2 * j + 1][2] - n1), p13 = __expf(Sx[2 * j + 1][3] - n1);
            lp0 += p00 + p01 + p10 + p11;
            lp1 += p02 + p03 + p12 + p13;
            pa[j][0] = h2u(__floats2half2_rn(p00, p01));
            pa[j][1] = h2u(__floats2half2_rn(p02, p03));
            pa[j][2] = h2u(__floats2half2_rn(p10, p11));
            pa[j][3] = h2u(__floats2half2_rn(p12, p13));
        }

        // O += P @ V   (V via ldmatrix.trans)
#pragma unroll
        for (int j = 0; j < 4; j++) {
#pragma unroll
            for (int g = 0; g < 8; g++) {
                uint32_t b[4];
                ldsm4t(b, vB + aswz(j * 16 + vrow, g * 2 + vc));
                mma16816(O[2 * g],     pa[j], b);
                mma16816(O[2 * g + 1], pa[j], b + 2);
            }
        }
        __syncthreads();
    }

    lp0 += __shfl_xor_sync(0xffffffffu, lp0, 1);
    lp0 += __shfl_xor_sync(0xffffffffu, lp0, 2);
    lp1 += __shfl_xor_sync(0xffffffffu, lp1, 1);
    lp1 += __shfl_xor_sync(0xffffffffu, lp1, 2);
    float rl0 = 1.0f / lp0, rl1 = 1.0f / lp1;

    const int ro0 = q0 + 16 * w + r0;
    const int ro1 = ro0 + 8;
    const int colb = (lane & 3) * 2;
    __half2* C2 = (__half2*)Ch;
#pragma unroll
    for (int nt = 0; nt < 16; nt++) {
        int col = nt * 8 + colb;
        C2[((size_t)ro0 * QDIM + h * HD + col) >> 1] = __floats2half2_rn(O[nt][0] * rl0, O[nt][1] * rl0);
        C2[((size_t)ro1 * QDIM + h * HD + col) >> 1] = __floats2half2_rn(O[nt][2] * rl1, O[nt][3] * rl1);
    }
}

// ============================================================
// launch
// ============================================================
extern "C" void kernel_launch(void* const* d_in, const int* in_sizes, int n_in,
                              void* d_out, int out_size) {
    const float* X   = (const float*)d_in[0];
    const int*   pos = (const int*)d_in[2];
    const float* wq  = (const float*)d_in[3];
    const float* wk  = (const float*)d_in[4];
    const float* wv  = (const float*)d_in[5];
    const float* wo  = (const float*)d_in[6];
    const float* qnw = (const float*)d_in[7];
    const float* knw = (const float*)d_in[8];
    float* out = (float*)d_out;

    float *Q, *Kb;
    float2* CS;
    cudaGetSymbolAddress((void**)&Q,  g_Q);
    cudaGetSymbolAddress((void**)&Kb, g_K);
    cudaGetSymbolAddress((void**)&CS, g_cs);

    __half *Xh, *Wqkvh, *Woh, *Qh, *Kh, *Vh, *Ch;
    cudaGetSymbolAddress((void**)&Xh,    g_Xh);
    cudaGetSymbolAddress((void**)&Wqkvh, g_Wqkvh);
    cudaGetSymbolAddress((void**)&Woh,   g_Woh);
    cudaGetSymbolAddress((void**)&Qh,    g_Qh);
    cudaGetSymbolAddress((void**)&Kh,    g_Kh);
    cudaGetSymbolAddress((void**)&Vh,    g_Vh);
    cudaGetSymbolAddress((void**)&Ch,    g_Ch);

    cudaFuncSetAttribute(gemm_qkv, cudaFuncAttributeMaxDynamicSharedMemorySize, GSMEM);
    cudaFuncSetAttribute(gemm_out, cudaFuncAttributeMaxDynamicSharedMemorySize, GSMEM);
    cudaFuncSetAttribute(attn_mma, cudaFuncAttributeMaxDynamicSharedMemorySize, ASM_TOT);

    const int T = 256;
    to_half<<<(S * HID / 4 + T - 1) / T, T>>>(X,  Xh,  S * HID / 4);
    to_half<<<(QDIM * HID / 4 + T - 1) / T, T>>>(wq, Wqkvh,                    QDIM * HID / 4);
    to_half<<<(KVDIM * HID / 4 + T - 1) / T, T>>>(wk, Wqkvh + QDIM * HID,      KVDIM * HID / 4);
    to_half<<<(KVDIM * HID / 4 + T - 1) / T, T>>>(wv, Wqkvh + (QDIM + KVDIM) * HID, KVDIM * HID / 4);
    to_half<<<(HID * QDIM / 4 + T - 1) / T, T>>>(wo, Woh, HID * QDIM / 4);
    cs_table<<<S, 64>>>(pos, CS);

    // fused Q/K/V projection (V straight to fp16)
    gemm_qkv<<<dim3(NQKV / BN, S / BM), 256, GSMEM>>>(Xh, Wqkvh, Q, Kb, Vh);

    const float scale = 0.08838834764831845f;   // 1/sqrt(128)
    rope_rms_h<<<dim3(S, NH),  64>>>(Q,  qnw, CS, QDIM,  scale, Qh);
    rope_rms_h<<<dim3(S, NKV), 64>>>(Kb, knw, CS, KVDIM, 1.0f,  Kh);

    attn_mma<<<dim3(S / AQT, NH), 128, ASM_TOT>>>(Qh, Kh, Vh, Ch);

    gemm_out<<<dim3(QDIM / BN, S / BM), 256, GSMEM>>>(Ch, Woh, out);
}

// round 11
// speedup vs baseline: 9.6304x; 1.0987x over previous
#include <cuda_runtime.h>
#include <cuda_fp16.h>
#include <cstdint>
#include <math.h>

// ---------------- problem constants ----------------
#define S       2048
#define HID     2048
#define NH      16
#define NKV     8
#define HD      128
#define QDIM    (NH*HD)    // 2048
#define KVDIM   (NKV*HD)   // 1024
#define KTOT    2048
#define NQKV    (QDIM + 2*KVDIM)   // 4096

// ---------------- scratch (no cudaMalloc allowed) ----------------
__device__ float2 g_cs[S * 64];
__device__ __half g_Xh[S * HID];
__device__ __half g_Wqkvh[NQKV * HID];      // Wq rows 0..2047, Wk 2048..3071, Wv 3072..4095
__device__ __half g_Woh[HID * QDIM];
__device__ __half g_Qh[S * QDIM];
__device__ __half g_Kh[S * KVDIM];
__device__ __half g_Vh[S * KVDIM];
__device__ __half g_Ch[S * QDIM];

// ================= PTX helpers (sm_80-era, valid on base sm_103) =================
__device__ __forceinline__ uint32_t smem_u32(const void* p) {
    uint32_t a;
    asm("{ .reg .u64 t; cvta.to.shared.u64 t, %1; cvt.u32.u64 %0, t; }" : "=r"(a) : "l"(p));
    return a;
}
__device__ __forceinline__ uint32_t h2u(__half2 h) {
    return *reinterpret_cast<uint32_t*>(&h);
}
__device__ __forceinline__ void cpasync16(uint32_t s, const void* g) {
    asm volatile("cp.async.cg.shared.global [%0], [%1], 16;" :: "r"(s), "l"(g));
}
__device__ __forceinline__ void ldsm4(uint32_t* r, uint32_t addr) {
    asm volatile("ldmatrix.sync.aligned.m8n8.x4.shared.b16 {%0,%1,%2,%3}, [%4];"
                 : "=r"(r[0]), "=r"(r[1]), "=r"(r[2]), "=r"(r[3]) : "r"(addr));
}
__device__ __forceinline__ void ldsm4t(uint32_t* r, uint32_t addr) {
    asm volatile("ldmatrix.sync.aligned.m8n8.x4.trans.shared.b16 {%0,%1,%2,%3}, [%4];"
                 : "=r"(r[0]), "=r"(r[1]), "=r"(r[2]), "=r"(r[3]) : "r"(addr));
}
__device__ __forceinline__ void mma16816(float* c, const uint32_t* a, const uint32_t* b) {
    asm volatile(
        "mma.sync.aligned.m16n8k16.row.col.f32.f16.f16.f32 "
        "{%0,%1,%2,%3}, {%4,%5,%6,%7}, {%8,%9}, {%0,%1,%2,%3};"
        : "+f"(c[0]), "+f"(c[1]), "+f"(c[2]), "+f"(c[3])
        : "r"(a[0]), "r"(a[1]), "r"(a[2]), "r"(a[3]), "r"(b[0]), "r"(b[1]));
}

// ============================================================
// One fused fp32 -> fp16 conversion over X + all weights
// ============================================================
#define N_X  (S * HID / 4)
#define N_WQ (QDIM * HID / 4)
#define N_WK (KVDIM * HID / 4)
#define N_WV (KVDIM * HID / 4)
#define N_WO (HID * QDIM / 4)
#define N_ALL (N_X + N_WQ + N_WK + N_WV + N_WO)   // 4194304

__global__ void conv_all(const float* __restrict__ X,  const float* __restrict__ wq,
                         const float* __restrict__ wk, const float* __restrict__ wv,
                         const float* __restrict__ wo,
                         __half* __restrict__ Xh, __half* __restrict__ Wqkvh,
                         __half* __restrict__ Woh) {
    int i = blockIdx.x * blockDim.x + threadIdx.x;
    if (i >= N_ALL) return;
    const float* src; __half* dst; int j;
    if (i < N_X)                       { src = X;  dst = Xh;                          j = i; }
    else if (i < N_X + N_WQ)           { src = wq; dst = Wqkvh;                       j = i - N_X; }
    else if (i < N_X + N_WQ + N_WK)    { src = wk; dst = Wqkvh + QDIM * HID;          j = i - N_X - N_WQ; }
    else if (i < N_X + N_WQ + N_WK + N_WV)
                                       { src = wv; dst = Wqkvh + (QDIM + KVDIM) * HID; j = i - N_X - N_WQ - N_WK; }
    else                               { src = wo; dst = Woh;                         j = i - N_X - N_WQ - N_WK - N_WV; }
    float4 v = ((const float4*)src)[j];
    __half2* Y = (__half2*)dst;
    Y[2 * j]     = __floats2half2_rn(v.x, v.y);
    Y[2 * j + 1] = __floats2half2_rn(v.z, v.w);
}

// ============================================================
// RoPE cos/sin table: one entry per (seq pos, freq idx 0..63)
// ============================================================
__global__ void cs_table(const int* __restrict__ pos_ids, float2* __restrict__ cs) {
    const int s = blockIdx.x;
    const int d = threadIdx.x;
    float pos = (float)pos_ids[s];
    const float NL2T_64 = 19.931568569324174f / 64.0f;
    float inv = exp2f(-(float)d * NL2T_64);
    float sn, c;
    sincosf(pos * inv, &sn, &c);
    cs[s * 64 + d] = make_float2(c, sn);
}

// ============================================================
// fp16 mma.sync GEMM mainloop (shared)
// CTA 128x128x32, 256 threads (8 warps 2m x 4n), warp tile 64x32.
// ============================================================
#define BM 128
#define BN 128
#define BK 32
#define NIT (KTOT / BK)          // 64
#define TILEB (BM * 64)          // 8KB per operand tile
#define STAGEB (2 * TILEB)       // A + B = 16KB
#define NSTAGE 4
#define GSMEM (NSTAGE * STAGEB)  // 64KB

__device__ __forceinline__ uint32_t swz(int row, int ci) {
    return (uint32_t)(row * 64 + ((ci ^ ((row >> 1) & 3)) << 4));
}

template <typename EpiF>
__device__ __forceinline__ void gemm_core(const __half* __restrict__ A,
                                          const __half* __restrict__ B,
                                          int m0, int bn0, char* smem, EpiF epi) {
    const uint32_t sb = smem_u32(smem);
    const int tid = threadIdx.x;
    const int lane = tid & 31;
    const int w = tid >> 5;
    const int wm = w & 1;
    const int wn = w >> 1;

    const int arow_l = (lane & 7) + ((lane >> 3) & 1) * 8;
    const int ahi_c  = lane >> 4;
    const int brow_l = (lane & 7) + ((lane >> 4) & 1) * 8;
    const int bhi_c  = (lane >> 3) & 1;
    uint32_t aoff[4], boff[2];
#pragma unroll
    for (int mi = 0; mi < 4; mi++) aoff[mi] = swz(wm * 64 + mi * 16 + arow_l, ahi_c);
#pragma unroll
    for (int nt = 0; nt < 2; nt++) boff[nt] = TILEB + swz(wn * 32 + nt * 16 + brow_l, bhi_c);

    const int grow = tid >> 2;
    const int gci  = tid & 3;

    float acc[4][4][4];
#pragma unroll
    for (int mi = 0; mi < 4; mi++)
#pragma unroll
        for (int ni = 0; ni < 4; ni++)
#pragma unroll
            for (int e = 0; e < 4; e++) acc[mi][ni][e] = 0.f;

    auto load_stage = [&](int it, int buf) {
        const int k0 = it * BK;
        const uint32_t st = sb + buf * STAGEB;
#pragma unroll
        for (int p = 0; p < 2; p++) {
            int row = grow + p * 64;
            uint32_t so = swz(row, gci);
            cpasync16(st + so,         A + (size_t)(m0 + row) * KTOT + k0 + gci * 8);
            cpasync16(st + TILEB + so, B + (size_t)(bn0 + row) * KTOT + k0 + gci * 8);
        }
    };

#pragma unroll
    for (int p = 0; p < 3; p++) {
        load_stage(p, p);
        asm volatile("cp.async.commit_group;" ::: "memory");
    }

    for (int it = 0; it < NIT; it++) {
        asm volatile("cp.async.wait_group 2;" ::: "memory");
        __syncthreads();

        const uint32_t st = sb + (it & 3) * STAGEB;
#pragma unroll
        for (int kc = 0; kc < 2; kc++) {
            const uint32_t kx = kc << 5;
            uint32_t ah[4][4], bh[4][2];
#pragma unroll
            for (int mi = 0; mi < 4; mi++) ldsm4(ah[mi], st + (aoff[mi] ^ kx));
#pragma unroll
            for (int nt = 0; nt < 2; nt++) {
                uint32_t t[4];
                ldsm4(t, st + (boff[nt] ^ kx));
                bh[2 * nt][0] = t[0]; bh[2 * nt][1] = t[1];
                bh[2 * nt + 1][0] = t[2]; bh[2 * nt + 1][1] = t[3];
            }
#pragma unroll
            for (int mi = 0; mi < 4; mi++)
#pragma unroll
                for (int ni = 0; ni < 4; ni++)
                    mma16816(acc[mi][ni], ah[mi], bh[ni]);
        }
        __syncthreads();

        if (it + 3 < NIT) load_stage(it + 3, (it + 3) & 3);
        asm volatile("cp.async.commit_group;" ::: "memory");
    }

    const int lrow = wm * 64 + (lane >> 2);
    const int lcol = wn * 32 + (lane & 3) * 2;
    epi(acc, lrow, lcol);
}

// ---- fused QKV projection: all outputs fp16 ----
__global__ __launch_bounds__(256)
void gemm_qkv(const __half* __restrict__ Xh, const __half* __restrict__ Wqkv,
              __half* __restrict__ Qh, __half* __restrict__ Kh, __half* __restrict__ Vh) {
    extern __shared__ char smem[];
    const int m0 = blockIdx.y * BM;
    const int n0 = blockIdx.x * BN;   // 0..4095

    __half* base; int stride, nn0;
    if (n0 < QDIM)              { base = Qh; stride = QDIM;  nn0 = n0; }
    else if (n0 < QDIM + KVDIM) { base = Kh; stride = KVDIM; nn0 = n0 - QDIM; }
    else                        { base = Vh; stride = KVDIM; nn0 = n0 - QDIM - KVDIM; }

    gemm_core(Xh, Wqkv, m0, n0, smem, [&](float a[4][4][4], int lr, int lc) {
#pragma unroll
        for (int mi = 0; mi < 4; mi++)
#pragma unroll
            for (int ni = 0; ni < 4; ni++) {
                __half* c0 = base + (size_t)(m0 + lr + mi * 16) * stride + nn0 + lc + ni * 8;
                *(__half2*)c0                = __floats2half2_rn(a[mi][ni][0], a[mi][ni][1]);
                *(__half2*)(c0 + 8 * stride) = __floats2half2_rn(a[mi][ni][2], a[mi][ni][3]);
            }
    });
}

// ---- output projection: fp32 out ----
__global__ __launch_bounds__(256)
void gemm_out(const __half* __restrict__ A, const __half* __restrict__ B,
              float* __restrict__ C) {
    extern __shared__ char smem[];
    const int m0 = blockIdx.y * BM;
    const int n0 = blockIdx.x * BN;
    gemm_core(A, B, m0, n0, smem, [&](float a[4][4][4], int lr, int lc) {
#pragma unroll
        for (int mi = 0; mi < 4; mi++)
#pragma unroll
            for (int ni = 0; ni < 4; ni++) {
                float* c0 = C + (size_t)(m0 + lr + mi * 16) * QDIM + n0 + lc + ni * 8;
                float* c1 = c0 + 8 * QDIM;
                *(float2*)c0 = make_float2(a[mi][ni][0], a[mi][ni][1]);
                *(float2*)c1 = make_float2(a[mi][ni][2], a[mi][ni][3]);
            }
    });
}

// ============================================================
// Fused RoPE + RMS-norm for Q and K, fp16 in-place, table-driven.
// grid (S, NH+NKV): blocks 0..15 -> Q head, 16..23 -> K head.
// ============================================================
__global__ void rope_rms_fused(__half* __restrict__ Qh, __half* __restrict__ Kh,
                               const float* __restrict__ qnw, const float* __restrict__ knw,
                               const float2* __restrict__ CS, float qscale) {
    const int s  = blockIdx.x;
    const int hh = blockIdx.y;
    const int d  = threadIdx.x;           // 0..63 (pair d, d+64)

    __half* x; const float* w; float osc;
    if (hh < NH) { x = Qh + (size_t)s * QDIM  + hh * HD;        w = qnw; osc = qscale; }
    else         { x = Kh + (size_t)s * KVDIM + (hh - NH) * HD; w = knw; osc = 1.0f;   }

    float2 cs = CS[s * 64 + d];
    float x1 = __half2float(x[d]), x2 = __half2float(x[d + 64]);
    float o1 = x1 * cs.x - x2 * cs.y;
    float o2 = x2 * cs.x + x1 * cs.y;

    float sq = o1 * o1 + o2 * o2;
#pragma unroll
    for (int off = 16; off; off >>= 1) sq += __shfl_xor_sync(0xffffffffu, sq, off);
    __shared__ float wsum[2];
    if ((threadIdx.x & 31) == 0) wsum[threadIdx.x >> 5] = sq;
    __syncthreads();
    float var = (wsum[0] + wsum[1]) * (1.0f / 128.0f);
    float r = rsqrtf(var + 1e-6f) * osc;

    x[d]      = __float2half_rn(o1 * r * w[d]);
    x[d + 64] = __float2half_rn(o2 * r * w[d + 64]);
}

// ============================================================
// fp16 tensor-core causal GQA flash attention, double-buffered K/V,
// Q fragments hoisted to registers.
// CTA: 4 warps, q-tile 64, kv-tile 64.
// ============================================================
#define AQT 64
#define AKT 64
#define ASM_Q 0
#define ASM_KV0 16384            // buf0: K@16K, V@32K; buf1: K@48K, V@64K
#define ASM_TOT 81920

__device__ __forceinline__ uint32_t aswz(int row, int c) {
    return (uint32_t)(row * 256 + ((c ^ (row & 7)) << 4));
}

__global__ __launch_bounds__(128)
void attn_mma(const __half* __restrict__ Qh, const __half* __restrict__ Kh,
              const __half* __restrict__ Vh, __half* __restrict__ Ch) {
    extern __shared__ char sm[];
    const uint32_t sb = smem_u32(sm);
    const int qt = (gridDim.x - 1) - blockIdx.x;    // heavy tiles first
    const int h  = blockIdx.y;
    const int kh = h >> 1;
    const int tid = threadIdx.x;
    const int lane = tid & 31;
    const int w = tid >> 5;
    const int q0 = qt * AQT;

    auto load_kv = [&](int t, int buf) {
        const int k0 = t * AKT;
        const uint32_t kb = sb + ASM_KV0 + buf * 32768;
#pragma unroll
        for (int i = 0; i < 8; i++) {
            int idx = tid + i * 128;
            int row = idx >> 4;
            int c   = idx & 15;
            cpasync16(kb + aswz(row, c),
                      Kh + (size_t)(k0 + row) * KVDIM + kh * HD + c * 8);
            cpasync16(kb + 16384 + aswz(row, c),
                      Vh + (size_t)(k0 + row) * KVDIM + kh * HD + c * 8);
        }
        asm volatile("cp.async.commit_group;" ::: "memory");
    };

    // load Q tile (64 x 128 fp16, swizzled)
#pragma unroll
    for (int i = 0; i < 8; i++) {
        int idx = tid + i * 128;
        int row = idx >> 4;
        int c   = idx & 15;
        cpasync16(sb + ASM_Q + aswz(row, c),
                  Qh + (size_t)(q0 + row) * QDIM + h * HD + c * 8);
    }
    asm volatile("cp.async.commit_group;" ::: "memory");
    load_kv(0, 0);

    const int arow = (lane & 7) + ((lane >> 3) & 1) * 8;
    const int ac   = lane >> 4;
    const int brow = (lane & 7) + ((lane >> 4) & 1) * 8;
    const int bc   = (lane >> 3) & 1;
    const int vrow = (lane & 7) + ((lane >> 3) & 1) * 8;
    const int vc   = lane >> 4;
    const int r0   = lane >> 2;

    // hoist Q fragments into registers (loop-invariant)
    asm volatile("cp.async.wait_group 1;" ::: "memory");
    __syncthreads();
    uint32_t qa[8][4];
#pragma unroll
    for (int kk = 0; kk < 8; kk++)
        ldsm4(qa[kk], sb + ASM_Q + aswz(16 * w + arow, kk * 2 + ac));

    float O[16][4];
#pragma unroll
    for (int nt = 0; nt < 16; nt++)
#pragma unroll
        for (int e = 0; e < 4; e++) O[nt][e] = 0.f;
    float m0 = -1e30f, m1 = -1e30f, lp0 = 0.f, lp1 = 0.f;

    for (int t = 0; t <= qt; t++) {
        const int buf = t & 1;
        if (t < qt) {
            load_kv(t + 1, buf ^ 1);
            asm volatile("cp.async.wait_group 1;" ::: "memory");
        } else {
            asm volatile("cp.async.wait_group 0;" ::: "memory");
        }
        __syncthreads();
        const uint32_t kB = sb + ASM_KV0 + buf * 32768;
        const uint32_t vB = kB + 16384;

        // scores S[16 x 64] for this warp
        float Sx[8][4];
#pragma unroll
        for (int nn = 0; nn < 8; nn++)
#pragma unroll
            for (int e = 0; e < 4; e++) Sx[nn][e] = 0.f;

#pragma unroll
        for (int kk = 0; kk < 8; kk++) {
#pragma unroll
            for (int nt = 0; nt < 4; nt++) {
                uint32_t b[4];
                ldsm4(b, kB + aswz(nt * 16 + brow, kk * 2 + bc));
                mma16816(Sx[2 * nt],     qa[kk], b);
                mma16816(Sx[2 * nt + 1], qa[kk], b + 2);
            }
        }

        if (t == qt) {   // diagonal tile: mask col > row
#pragma unroll
            for (int nn = 0; nn < 8; nn++)
#pragma unroll
                for (int e = 0; e < 4; e++) {
                    int col = nn * 8 + (lane & 3) * 2 + (e & 1);
                    int row = 16 * w + r0 + 8 * (e >> 1);
                    if (col > row) Sx[nn][e] = -1e30f;
                }
        }

        // online softmax (rows r0 and r0+8)
        float t0 = -1e30f, t1 = -1e30f;
#pragma unroll
        for (int nn = 0; nn < 8; nn++) {
            t0 = fmaxf(t0, fmaxf(Sx[nn][0], Sx[nn][1]));
            t1 = fmaxf(t1, fmaxf(Sx[nn][2], Sx[nn][3]));
        }
        t0 = fmaxf(t0, __shfl_xor_sync(0xffffffffu, t0, 1));
        t0 = fmaxf(t0, __shfl_xor_sync(0xffffffffu, t0, 2));
        t1 = fmaxf(t1, __shfl_xor_sync(0xffffffffu, t1, 1));
        t1 = fmaxf(t1, __shfl_xor_sync(0xffffffffu, t1, 2));
        float n0 = fmaxf(m0, t0), n1 = fmaxf(m1, t1);
        float a0 = __expf(m0 - n0), a1 = __expf(m1 - n1);
        m0 = n0; m1 = n1; lp0 *= a0; lp1 *= a1;
#pragma unroll
        for (int nt = 0; nt < 16; nt++) {
            O[nt][0] *= a0; O[nt][1] *= a0; O[nt][2] *= a1; O[nt][3] *= a1;
        }

        uint32_t pa[4][4];
#pragma unroll
        for (int j = 0; j < 4; j++) {
            float p00 = __expf(Sx[2 * j][0] - n0),     p01 = __expf(Sx[2 * j][1] - n0);
            float p02 = __expf(Sx[2 * j][2] - n1),     p03 = __expf(Sx[2 * j][3] - n1);
            float p10 = __expf(Sx[2 * j + 1][0] - n0), p11 = __expf(Sx[2 * j + 1][1] - n0);
            float p12 = __expf(Sx[2 * j + 1][2] - n1), p13 = __expf(Sx[2 * j + 1][3] - n1);
            lp0 += p00 + p01 + p10 + p11;
            lp1 += p02 + p03 + p12 + p13;
            pa[j][0] = h2u(__floats2half2_rn(p00, p01));
            pa[j][1] = h2u(__floats2half2_rn(p02, p03));
            pa[j][2] = h2u(__floats2half2_rn(p10, p11));
            pa[j][3] = h2u(__floats2half2_rn(p12, p13));
        }

        // O += P @ V   (V via ldmatrix.trans)
#pragma unroll
        for (int j = 0; j < 4; j++) {
#pragma unroll
            for (int g = 0; g < 8; g++) {
                uint32_t b[4];
                ldsm4t(b, vB + aswz(j * 16 + vrow, g * 2 + vc));
                mma16816(O[2 * g],     pa[j], b);
                mma16816(O[2 * g + 1], pa[j], b + 2);
            }
        }
        __syncthreads();
    }

    lp0 += __shfl_xor_sync(0xffffffffu, lp0, 1);
    lp0 += __shfl_xor_sync(0xffffffffu, lp0, 2);
    lp1 += __shfl_xor_sync(0xffffffffu, lp1, 1);
    lp1 += __shfl_xor_sync(0xffffffffu, lp1, 2);
    float rl0 = 1.0f / lp0, rl1 = 1.0f / lp1;

    const int ro0 = q0 + 16 * w + r0;
    const int ro1 = ro0 + 8;
    const int colb = (lane & 3) * 2;
    __half2* C2 = (__half2*)Ch;
#pragma unroll
    for (int nt = 0; nt < 16; nt++) {
        int col = nt * 8 + colb;
        C2[((size_t)ro0 * QDIM + h * HD + col) >> 1] = __floats2half2_rn(O[nt][0] * rl0, O[nt][1] * rl0);
        C2[((size_t)ro1 * QDIM + h * HD + col) >> 1] = __floats2half2_rn(O[nt][2] * rl1, O[nt][3] * rl1);
    }
}

// ============================================================
// launch
// ============================================================
extern "C" void kernel_launch(void* const* d_in, const int* in_sizes, int n_in,
                              void* d_out, int out_size) {
    const float* X   = (const float*)d_in[0];
    const int*   pos = (const int*)d_in[2];
    const float* wq  = (const float*)d_in[3];
    const float* wk  = (const float*)d_in[4];
    const float* wv  = (const float*)d_in[5];
    const float* wo  = (const float*)d_in[6];
    const float* qnw = (const float*)d_in[7];
    const float* knw = (const float*)d_in[8];
    float* out = (float*)d_out;

    float2* CS;
    cudaGetSymbolAddress((void**)&CS, g_cs);

    __half *Xh, *Wqkvh, *Woh, *Qh, *Kh, *Vh, *Ch;
    cudaGetSymbolAddress((void**)&Xh,    g_Xh);
    cudaGetSymbolAddress((void**)&Wqkvh, g_Wqkvh);
    cudaGetSymbolAddress((void**)&Woh,   g_Woh);
    cudaGetSymbolAddress((void**)&Qh,    g_Qh);
    cudaGetSymbolAddress((void**)&Kh,    g_Kh);
    cudaGetSymbolAddress((void**)&Vh,    g_Vh);
    cudaGetSymbolAddress((void**)&Ch,    g_Ch);

    cudaFuncSetAttribute(gemm_qkv, cudaFuncAttributeMaxDynamicSharedMemorySize, GSMEM);
    cudaFuncSetAttribute(gemm_out, cudaFuncAttributeMaxDynamicSharedMemorySize, GSMEM);
    cudaFuncSetAttribute(attn_mma, cudaFuncAttributeMaxDynamicSharedMemorySize, ASM_TOT);

    const int T = 256;
    conv_all<<<(N_ALL + T - 1) / T, T>>>(X, wq, wk, wv, wo, Xh, Wqkvh, Woh);
    cs_table<<<S, 64>>>(pos, CS);

    // fused Q/K/V projection, all fp16 outputs
    gemm_qkv<<<dim3(NQKV / BN, S / BM), 256, GSMEM>>>(Xh, Wqkvh, Qh, Kh, Vh);

    const float scale = 0.08838834764831845f;   // 1/sqrt(128)
    rope_rms_fused<<<dim3(S, NH + NKV), 64>>>(Qh, Kh, qnw, knw, CS, scale);

    attn_mma<<<dim3(S / AQT, NH), 128, ASM_TOT>>>(Qh, Kh, Vh, Ch);

    gemm_out<<<dim3(QDIM / BN, S / BM), 256, GSMEM>>>(Ch, Woh, out);
}

// round 12
// speedup vs baseline: 10.2232x; 1.0616x over previous
#include <cuda_runtime.h>
#include <cuda_fp16.h>
#include <cstdint>
#include <math.h>

// ---------------- problem constants ----------------
#define S       2048
#define HID     2048
#define NH      16
#define NKV     8
#define HD      128
#define QDIM    (NH*HD)    // 2048
#define KVDIM   (NKV*HD)   // 1024
#define KTOT    2048
#define NQKV    (QDIM + 2*KVDIM)   // 4096

// ---------------- scratch (no cudaMalloc allowed) ----------------
__device__ float2 g_cs[S * 64];
__device__ __half g_Xh[S * HID];
__device__ __half g_Wqkvh[NQKV * HID];
__device__ __half g_Woh[HID * QDIM];
__device__ __half g_Qh[S * QDIM];
__device__ __half g_Kh[S * KVDIM];
__device__ __half g_Vh[S * KVDIM];
__device__ __half g_Ch[S * QDIM];

// ================= PTX helpers =================
__device__ __forceinline__ uint32_t smem_u32(const void* p) {
    uint32_t a;
    asm("{ .reg .u64 t; cvta.to.shared.u64 t, %1; cvt.u32.u64 %0, t; }" : "=r"(a) : "l"(p));
    return a;
}
__device__ __forceinline__ uint32_t h2u(__half2 h) {
    return *reinterpret_cast<uint32_t*>(&h);
}
__device__ __forceinline__ void cpasync16(uint32_t s, const void* g) {
    asm volatile("cp.async.cg.shared.global [%0], [%1], 16;" :: "r"(s), "l"(g));
}
__device__ __forceinline__ void ldsm4(uint32_t* r, uint32_t addr) {
    asm volatile("ldmatrix.sync.aligned.m8n8.x4.shared.b16 {%0,%1,%2,%3}, [%4];"
                 : "=r"(r[0]), "=r"(r[1]), "=r"(r[2]), "=r"(r[3]) : "r"(addr));
}
__device__ __forceinline__ void ldsm4t(uint32_t* r, uint32_t addr) {
    asm volatile("ldmatrix.sync.aligned.m8n8.x4.trans.shared.b16 {%0,%1,%2,%3}, [%4];"
                 : "=r"(r[0]), "=r"(r[1]), "=r"(r[2]), "=r"(r[3]) : "r"(addr));
}
__device__ __forceinline__ void mma16816(float* c, const uint32_t* a, const uint32_t* b) {
    asm volatile(
        "mma.sync.aligned.m16n8k16.row.col.f32.f16.f16.f32 "
        "{%0,%1,%2,%3}, {%4,%5,%6,%7}, {%8,%9}, {%0,%1,%2,%3};"
        : "+f"(c[0]), "+f"(c[1]), "+f"(c[2]), "+f"(c[3])
        : "r"(a[0]), "r"(a[1]), "r"(a[2]), "r"(a[3]), "r"(b[0]), "r"(b[1]));
}

// ============================================================
// One fused fp32 -> fp16 conversion over X + all weights
// ============================================================
#define N_X  (S * HID / 4)
#define N_WQ (QDIM * HID / 4)
#define N_WK (KVDIM * HID / 4)
#define N_WV (KVDIM * HID / 4)
#define N_WO (HID * QDIM / 4)
#define N_ALL (N_X + N_WQ + N_WK + N_WV + N_WO)

__global__ void conv_all(const float* __restrict__ X,  const float* __restrict__ wq,
                         const float* __restrict__ wk, const float* __restrict__ wv,
                         const float* __restrict__ wo,
                         __half* __restrict__ Xh, __half* __restrict__ Wqkvh,
                         __half* __restrict__ Woh) {
    int i = blockIdx.x * blockDim.x + threadIdx.x;
    if (i >= N_ALL) return;
    const float* src; __half* dst; int j;
    if (i < N_X)                       { src = X;  dst = Xh;                          j = i; }
    else if (i < N_X + N_WQ)           { src = wq; dst = Wqkvh;                       j = i - N_X; }
    else if (i < N_X + N_WQ + N_WK)    { src = wk; dst = Wqkvh + QDIM * HID;          j = i - N_X - N_WQ; }
    else if (i < N_X + N_WQ + N_WK + N_WV)
                                       { src = wv; dst = Wqkvh + (QDIM + KVDIM) * HID; j = i - N_X - N_WQ - N_WK; }
    else                               { src = wo; dst = Woh;                         j = i - N_X - N_WQ - N_WK - N_WV; }
    float4 v = ((const float4*)src)[j];
    __half2* Y = (__half2*)dst;
    Y[2 * j]     = __floats2half2_rn(v.x, v.y);
    Y[2 * j + 1] = __floats2half2_rn(v.z, v.w);
}

// ============================================================
// RoPE cos/sin table
// ============================================================
__global__ void cs_table(const int* __restrict__ pos_ids, float2* __restrict__ cs) {
    const int s = blockIdx.x;
    const int d = threadIdx.x;
    float pos = (float)pos_ids[s];
    const float NL2T_64 = 19.931568569324174f / 64.0f;
    float inv = exp2f(-(float)d * NL2T_64);
    float sn, c;
    sincosf(pos * inv, &sn, &c);
    cs[s * 64 + d] = make_float2(c, sn);
}

// ============================================================
// fp16 mma.sync GEMM mainloop (shared)
// ============================================================
#define BM 128
#define BN 128
#define BK 32
#define NIT (KTOT / BK)
#define TILEB (BM * 64)
#define STAGEB (2 * TILEB)
#define NSTAGE 4
#define GSMEM (NSTAGE * STAGEB)

__device__ __forceinline__ uint32_t swz(int row, int ci) {
    return (uint32_t)(row * 64 + ((ci ^ ((row >> 1) & 3)) << 4));
}

template <typename EpiF>
__device__ __forceinline__ void gemm_core(const __half* __restrict__ A,
                                          const __half* __restrict__ B,
                                          int m0, int bn0, char* smem, EpiF epi) {
    const uint32_t sb = smem_u32(smem);
    const int tid = threadIdx.x;
    const int lane = tid & 31;
    const int w = tid >> 5;
    const int wm = w & 1;
    const int wn = w >> 1;

    const int arow_l = (lane & 7) + ((lane >> 3) & 1) * 8;
    const int ahi_c  = lane >> 4;
    const int brow_l = (lane & 7) + ((lane >> 4) & 1) * 8;
    const int bhi_c  = (lane >> 3) & 1;
    uint32_t aoff[4], boff[2];
#pragma unroll
    for (int mi = 0; mi < 4; mi++) aoff[mi] = swz(wm * 64 + mi * 16 + arow_l, ahi_c);
#pragma unroll
    for (int nt = 0; nt < 2; nt++) boff[nt] = TILEB + swz(wn * 32 + nt * 16 + brow_l, bhi_c);

    const int grow = tid >> 2;
    const int gci  = tid & 3;

    float acc[4][4][4];
#pragma unroll
    for (int mi = 0; mi < 4; mi++)
#pragma unroll
        for (int ni = 0; ni < 4; ni++)
#pragma unroll
            for (int e = 0; e < 4; e++) acc[mi][ni][e] = 0.f;

    auto load_stage = [&](int it, int buf) {
        const int k0 = it * BK;
        const uint32_t st = sb + buf * STAGEB;
#pragma unroll
        for (int p = 0; p < 2; p++) {
            int row = grow + p * 64;
            uint32_t so = swz(row, gci);
            cpasync16(st + so,         A + (size_t)(m0 + row) * KTOT + k0 + gci * 8);
            cpasync16(st + TILEB + so, B + (size_t)(bn0 + row) * KTOT + k0 + gci * 8);
        }
    };

#pragma unroll
    for (int p = 0; p < 3; p++) {
        load_stage(p, p);
        asm volatile("cp.async.commit_group;" ::: "memory");
    }

    for (int it = 0; it < NIT; it++) {
        asm volatile("cp.async.wait_group 2;" ::: "memory");
        __syncthreads();

        const uint32_t st = sb + (it & 3) * STAGEB;
#pragma unroll
        for (int kc = 0; kc < 2; kc++) {
            const uint32_t kx = kc << 5;
            uint32_t ah[4][4], bh[4][2];
#pragma unroll
            for (int mi = 0; mi < 4; mi++) ldsm4(ah[mi], st + (aoff[mi] ^ kx));
#pragma unroll
            for (int nt = 0; nt < 2; nt++) {
                uint32_t t[4];
                ldsm4(t, st + (boff[nt] ^ kx));
                bh[2 * nt][0] = t[0]; bh[2 * nt][1] = t[1];
                bh[2 * nt + 1][0] = t[2]; bh[2 * nt + 1][1] = t[3];
            }
#pragma unroll
            for (int mi = 0; mi < 4; mi++)
#pragma unroll
                for (int ni = 0; ni < 4; ni++)
                    mma16816(acc[mi][ni], ah[mi], bh[ni]);
        }
        __syncthreads();

        if (it + 3 < NIT) load_stage(it + 3, (it + 3) & 3);
        asm volatile("cp.async.commit_group;" ::: "memory");
    }

    const int lrow = wm * 64 + (lane >> 2);
    const int lcol = wn * 32 + (lane & 3) * 2;
    epi(acc, lrow, lcol);
}

// ---- fused QKV projection: all outputs fp16 ----
__global__ __launch_bounds__(256)
void gemm_qkv(const __half* __restrict__ Xh, const __half* __restrict__ Wqkv,
              __half* __restrict__ Qh, __half* __restrict__ Kh, __half* __restrict__ Vh) {
    extern __shared__ char smem[];
    const int m0 = blockIdx.y * BM;
    const int n0 = blockIdx.x * BN;

    __half* base; int stride, nn0;
    if (n0 < QDIM)              { base = Qh; stride = QDIM;  nn0 = n0; }
    else if (n0 < QDIM + KVDIM) { base = Kh; stride = KVDIM; nn0 = n0 - QDIM; }
    else                        { base = Vh; stride = KVDIM; nn0 = n0 - QDIM - KVDIM; }

    gemm_core(Xh, Wqkv, m0, n0, smem, [&](float a[4][4][4], int lr, int lc) {
#pragma unroll
        for (int mi = 0; mi < 4; mi++)
#pragma unroll
            for (int ni = 0; ni < 4; ni++) {
                __half* c0 = base + (size_t)(m0 + lr + mi * 16) * stride + nn0 + lc + ni * 8;
                *(__half2*)c0                = __floats2half2_rn(a[mi][ni][0], a[mi][ni][1]);
                *(__half2*)(c0 + 8 * stride) = __floats2half2_rn(a[mi][ni][2], a[mi][ni][3]);
            }
    });
}

// ---- output projection: fp32 out ----
__global__ __launch_bounds__(256)
void gemm_out(const __half* __restrict__ A, const __half* __restrict__ B,
              float* __restrict__ C) {
    extern __shared__ char smem[];
    const int m0 = blockIdx.y * BM;
    const int n0 = blockIdx.x * BN;
    gemm_core(A, B, m0, n0, smem, [&](float a[4][4][4], int lr, int lc) {
#pragma unroll
        for (int mi = 0; mi < 4; mi++)
#pragma unroll
            for (int ni = 0; ni < 4; ni++) {
                float* c0 = C + (size_t)(m0 + lr + mi * 16) * QDIM + n0 + lc + ni * 8;
                float* c1 = c0 + 8 * QDIM;
                *(float2*)c0 = make_float2(a[mi][ni][0], a[mi][ni][1]);
                *(float2*)c1 = make_float2(a[mi][ni][2], a[mi][ni][3]);
            }
    });
}

// ============================================================
// Warp-per-head RoPE + RMS-norm, fp16 in-place, fully vectorized.
// 256 threads = 8 warps; warp = one (s, head) row. No block barrier.
// ============================================================
#define NROWS (S * (NH + NKV))   // 49152

__global__ __launch_bounds__(256)
void rope_rms_warp(__half* __restrict__ Qh, __half* __restrict__ Kh,
                   const float* __restrict__ qnw, const float* __restrict__ knw,
                   const float2* __restrict__ CS, float qscale) {
    const int gw   = (blockIdx.x * 256 + threadIdx.x) >> 5;   // global warp id
    const int lane = threadIdx.x & 31;
    const int hh = gw % (NH + NKV);
    const int s  = gw / (NH + NKV);

    __half2* x; const float* w; float osc;
    if (hh < NH) { x = (__half2*)(Qh + (size_t)s * QDIM  + hh * HD);        w = qnw; osc = qscale; }
    else         { x = (__half2*)(Kh + (size_t)s * KVDIM + (hh - NH) * HD); w = knw; osc = 1.0f;   }

    // lane covers elements (2l, 2l+1) paired with (2l+64, 2l+65)
    float2 cs0 = CS[s * 64 + 2 * lane];
    float2 cs1 = CS[s * 64 + 2 * lane + 1];
    float2 x1 = __half22float2(x[lane]);
    float2 x2 = __half22float2(x[lane + 32]);

    float o1x = x1.x * cs0.x - x2.x * cs0.y;
    float o1y = x1.y * cs1.x - x2.y * cs1.y;
    float o2x = x2.x * cs0.x + x1.x * cs0.y;
    float o2y = x2.y * cs1.x + x1.y * cs1.y;

    float sq = o1x * o1x + o1y * o1y + o2x * o2x + o2y * o2y;
#pragma unroll
    for (int off = 16; off; off >>= 1) sq += __shfl_xor_sync(0xffffffffu, sq, off);
    float r = rsqrtf(sq * (1.0f / 128.0f) + 1e-6f) * osc;

    float2 wa = ((const float2*)w)[lane];
    float2 wb = ((const float2*)w)[lane + 32];
    x[lane]      = __floats2half2_rn(o1x * r * wa.x, o1y * r * wa.y);
    x[lane + 32] = __floats2half2_rn(o2x * r * wb.x, o2y * r * wb.y);
}

// ============================================================
// fp16 tensor-core causal GQA flash attention, 3-stage KV ring,
// Q fragments hoisted; one barrier per kv tile.
// CTA: 4 warps, q-tile 64, kv-tile 64.
// ============================================================
#define AQT 64
#define AKT 64
#define ASM_Q 0
#define ASM_KV0 16384            // 3 stages of 32KB (K 16K + V 16K)
#define ASM_TOT (16384 + 3 * 32768)   // 114688

__device__ __forceinline__ uint32_t aswz(int row, int c) {
    return (uint32_t)(row * 256 + ((c ^ (row & 7)) << 4));
}

__global__ __launch_bounds__(128)
void attn_mma(const __half* __restrict__ Qh, const __half* __restrict__ Kh,
              const __half* __restrict__ Vh, __half* __restrict__ Ch) {
    extern __shared__ char sm[];
    const uint32_t sb = smem_u32(sm);
    const int qt = (gridDim.x - 1) - blockIdx.x;    // heavy tiles first
    const int h  = blockIdx.y;
    const int kh = h >> 1;
    const int tid = threadIdx.x;
    const int lane = tid & 31;
    const int w = tid >> 5;
    const int q0 = qt * AQT;

    auto load_kv = [&](int t) {
        const int k0 = t * AKT;
        const uint32_t kb = sb + ASM_KV0 + (t % 3) * 32768;
#pragma unroll
        for (int i = 0; i < 8; i++) {
            int idx = tid + i * 128;
            int row = idx >> 4;
            int c   = idx & 15;
            cpasync16(kb + aswz(row, c),
                      Kh + (size_t)(k0 + row) * KVDIM + kh * HD + c * 8);
            cpasync16(kb + 16384 + aswz(row, c),
                      Vh + (size_t)(k0 + row) * KVDIM + kh * HD + c * 8);
        }
        asm volatile("cp.async.commit_group;" ::: "memory");
    };

    // Q tile (group 0), kv(0) (group 1), kv(1) (group 2)
#pragma unroll
    for (int i = 0; i < 8; i++) {
        int idx = tid + i * 128;
        int row = idx >> 4;
        int c   = idx & 15;
        cpasync16(sb + ASM_Q + aswz(row, c),
                  Qh + (size_t)(q0 + row) * QDIM + h * HD + c * 8);
    }
    asm volatile("cp.async.commit_group;" ::: "memory");
    load_kv(0);
    if (qt >= 1) load_kv(1);

    const int arow = (lane & 7) + ((lane >> 3) & 1) * 8;
    const int ac   = lane >> 4;
    const int brow = (lane & 7) + ((lane >> 4) & 1) * 8;
    const int bc   = (lane >> 3) & 1;
    const int vrow = (lane & 7) + ((lane >> 3) & 1) * 8;
    const int vc   = lane >> 4;
    const int r0   = lane >> 2;

    // wait for Q only (leave kv groups in flight), hoist Q fragments
    if (qt >= 1) { asm volatile("cp.async.wait_group 2;" ::: "memory"); }
    else         { asm volatile("cp.async.wait_group 1;" ::: "memory"); }
    __syncthreads();
    uint32_t qa[8][4];
#pragma unroll
    for (int kk = 0; kk < 8; kk++)
        ldsm4(qa[kk], sb + ASM_Q + aswz(16 * w + arow, kk * 2 + ac));

    float O[16][4];
#pragma unroll
    for (int nt = 0; nt < 16; nt++)
#pragma unroll
        for (int e = 0; e < 4; e++) O[nt][e] = 0.f;
    float m0 = -1e30f, m1 = -1e30f, lp0 = 0.f, lp1 = 0.f;

    for (int t = 0; t <= qt; t++) {
        // ensure kv(t) arrived: outstanding = kv(t) [.. kv(t+1)]
        if (t < qt) { asm volatile("cp.async.wait_group 1;" ::: "memory"); }
        else        { asm volatile("cp.async.wait_group 0;" ::: "memory"); }
        __syncthreads();
        // prefetch kv(t+2): its buffer ((t+2)%3) was last read at iter t-1,
        // and the barrier above orders all compute(t-1) before these writes.
        if (t + 2 <= qt) load_kv(t + 2);

        const uint32_t kB = sb + ASM_KV0 + (t % 3) * 32768;
        const uint32_t vB = kB + 16384;

        float Sx[8][4];
#pragma unroll
        for (int nn = 0; nn < 8; nn++)
#pragma unroll
            for (int e = 0; e < 4; e++) Sx[nn][e] = 0.f;

#pragma unroll
        for (int kk = 0; kk < 8; kk++) {
#pragma unroll
            for (int nt = 0; nt < 4; nt++) {
                uint32_t b[4];
                ldsm4(b, kB + aswz(nt * 16 + brow, kk * 2 + bc));
                mma16816(Sx[2 * nt],     qa[kk], b);
                mma16816(Sx[2 * nt + 1], qa[kk], b + 2);
            }
        }

        if (t == qt) {   // diagonal tile: mask col > row
#pragma unroll
            for (int nn = 0; nn < 8; nn++)
#pragma unroll
                for (int e = 0; e < 4; e++) {
                    int col = nn * 8 + (lane & 3) * 2 + (e & 1);
                    int row = 16 * w + r0 + 8 * (e >> 1);
                    if (col > row) Sx[nn][e] = -1e30f;
                }
        }

        float t0 = -1e30f, t1 = -1e30f;
#pragma unroll
        for (int nn = 0; nn < 8; nn++) {
            t0 = fmaxf(t0, fmaxf(Sx[nn][0], Sx[nn][1]));
            t1 = fmaxf(t1, fmaxf(Sx[nn][2], Sx[nn][3]));
        }
        t0 = fmaxf(t0, __shfl_xor_sync(0xffffffffu, t0, 1));
        t0 = fmaxf(t0, __shfl_xor_sync(0xffffffffu, t0, 2));
        t1 = fmaxf(t1, __shfl_xor_sync(0xffffffffu, t1, 1));
        t1 = fmaxf(t1, __shfl_xor_sync(0xffffffffu, t1, 2));
        float n0 = fmaxf(m0, t0), n1 = fmaxf(m1, t1);
        float a0 = __expf(m0 - n0), a1 = __expf(m1 - n1);
        m0 = n0; m1 = n1; lp0 *= a0; lp1 *= a1;
#pragma unroll
        for (int nt = 0; nt < 16; nt++) {
            O[nt][0] *= a0; O[nt][1] *= a0; O[nt][2] *= a1; O[nt][3] *= a1;
        }

        uint32_t pa[4][4];
#pragma unroll
        for (int j = 0; j < 4; j++) {
            float p00 = __expf(Sx[2 * j][0] - n0),     p01 = __expf(Sx[2 * j][1] - n0);
            float p02 = __expf(Sx[2 * j][2] - n1),     p03 = __expf(Sx[2 * j][3] - n1);
            float p10 = __expf(Sx[2 * j + 1][0] - n0), p11 = __expf(Sx[2 * j + 1][1] - n0);
            float p12 = __expf(Sx[2 * j + 1][2] - n1), p13 = __expf(Sx[2 * j + 1][3] - n1);
            lp0 += p00 + p01 + p10 + p11;
            lp1 += p02 + p03 + p12 + p13;
            pa[j][0] = h2u(__floats2half2_rn(p00, p01));
            pa[j][1] = h2u(__floats2half2_rn(p02, p03));
            pa[j][2] = h2u(__floats2half2_rn(p10, p11));
            pa[j][3] = h2u(__floats2half2_rn(p12, p13));
        }

#pragma unroll
        for (int j = 0; j < 4; j++) {
#pragma unroll
            for (int g = 0; g < 8; g++) {
                uint32_t b[4];
                ldsm4t(b, vB + aswz(j * 16 + vrow, g * 2 + vc));
                mma16816(O[2 * g],     pa[j], b);
                mma16816(O[2 * g + 1], pa[j], b + 2);
            }
        }
        // no trailing barrier: buffer reuse ordered by next iteration's barrier
    }

    lp0 += __shfl_xor_sync(0xffffffffu, lp0, 1);
    lp0 += __shfl_xor_sync(0xffffffffu, lp0, 2);
    lp1 += __shfl_xor_sync(0xffffffffu, lp1, 1);
    lp1 += __shfl_xor_sync(0xffffffffu, lp1, 2);
    float rl0 = 1.0f / lp0, rl1 = 1.0f / lp1;

    const int ro0 = q0 + 16 * w + r0;
    const int ro1 = ro0 + 8;
    const int colb = (lane & 3) * 2;
    __half2* C2 = (__half2*)Ch;
#pragma unroll
    for (int nt = 0; nt < 16; nt++) {
        int col = nt * 8 + colb;
        C2[((size_t)ro0 * QDIM + h * HD + col) >> 1] = __floats2half2_rn(O[nt][0] * rl0, O[nt][1] * rl0);
        C2[((size_t)ro1 * QDIM + h * HD + col) >> 1] = __floats2half2_rn(O[nt][2] * rl1, O[nt][3] * rl1);
    }
}

// ============================================================
// launch
// ============================================================
extern "C" void kernel_launch(void* const* d_in, const int* in_sizes, int n_in,
                              void* d_out, int out_size) {
    const float* X   = (const float*)d_in[0];
    const int*   pos = (const int*)d_in[2];
    const float* wq  = (const float*)d_in[3];
    const float* wk  = (const float*)d_in[4];
    const float* wv  = (const float*)d_in[5];
    const float* wo  = (const float*)d_in[6];
    const float* qnw = (const float*)d_in[7];
    const float* knw = (const float*)d_in[8];
    float* out = (float*)d_out;

    float2* CS;
    cudaGetSymbolAddress((void**)&CS, g_cs);

    __half *Xh, *Wqkvh, *Woh, *Qh, *Kh, *Vh, *Ch;
    cudaGetSymbolAddress((void**)&Xh,    g_Xh);
    cudaGetSymbolAddress((void**)&Wqkvh, g_Wqkvh);
    cudaGetSymbolAddress((void**)&Woh,   g_Woh);
    cudaGetSymbolAddress((void**)&Qh,    g_Qh);
    cudaGetSymbolAddress((void**)&Kh,    g_Kh);
    cudaGetSymbolAddress((void**)&Vh,    g_Vh);
    cudaGetSymbolAddress((void**)&Ch,    g_Ch);

    cudaFuncSetAttribute(gemm_qkv, cudaFuncAttributeMaxDynamicSharedMemorySize, GSMEM);
    cudaFuncSetAttribute(gemm_out, cudaFuncAttributeMaxDynamicSharedMemorySize, GSMEM);
    cudaFuncSetAttribute(attn_mma, cudaFuncAttributeMaxDynamicSharedMemorySize, ASM_TOT);

    const int T = 256;
    conv_all<<<(N_ALL + T - 1) / T, T>>>(X, wq, wk, wv, wo, Xh, Wqkvh, Woh);
    cs_table<<<S, 64>>>(pos, CS);

    gemm_qkv<<<dim3(NQKV / BN, S / BM), 256, GSMEM>>>(Xh, Wqkvh, Qh, Kh, Vh);

    const float scale = 0.08838834764831845f;   // 1/sqrt(128)
    rope_rms_warp<<<NROWS / 8, 256>>>(Qh, Kh, qnw, knw, CS, scale);

    attn_mma<<<dim3(S / AQT, NH), 128, ASM_TOT>>>(Qh, Kh, Vh, Ch);

    gemm_out<<<dim3(QDIM / BN, S / BM), 256, GSMEM>>>(Ch, Woh, out);
}

// round 13
// speedup vs baseline: 10.3612x; 1.0135x over previous
#include <cuda_runtime.h>
#include <cuda_fp16.h>
#include <cstdint>
#include <math.h>

// ---------------- problem constants ----------------
#define S       2048
#define HID     2048
#define NH      16
#define NKV     8
#define HD      128
#define QDIM    (NH*HD)    // 2048
#define KVDIM   (NKV*HD)   // 1024
#define KTOT    2048
#define NQKV    (QDIM + 2*KVDIM)   // 4096

// ---------------- scratch ----------------
__device__ float2 g_cs[S * 64];
__device__ __half g_Xh[S * HID];
__device__ __half g_Wqkvh[NQKV * HID];
__device__ __half g_Woh[HID * QDIM];
__device__ __half g_Qh[S * QDIM];
__device__ __half g_Kh[S * KVDIM];
__device__ __half g_Vh[S * KVDIM];
__device__ __half g_Ch[S * QDIM];

// ================= PTX helpers =================
__device__ __forceinline__ uint32_t smem_u32(const void* p) {
    uint32_t a;
    asm("{ .reg .u64 t; cvta.to.shared.u64 t, %1; cvt.u32.u64 %0, t; }" : "=r"(a) : "l"(p));
    return a;
}
__device__ __forceinline__ uint32_t h2u(__half2 h) {
    return *reinterpret_cast<uint32_t*>(&h);
}
__device__ __forceinline__ float ex2(float x) {
    float r;
    asm("ex2.approx.ftz.f32 %0, %1;" : "=f"(r) : "f"(x));
    return r;
}
__device__ __forceinline__ void cpasync16(uint32_t s, const void* g) {
    asm volatile("cp.async.cg.shared.global [%0], [%1], 16;" :: "r"(s), "l"(g));
}
__device__ __forceinline__ void ldsm4(uint32_t* r, uint32_t addr) {
    asm volatile("ldmatrix.sync.aligned.m8n8.x4.shared.b16 {%0,%1,%2,%3}, [%4];"
                 : "=r"(r[0]), "=r"(r[1]), "=r"(r[2]), "=r"(r[3]) : "r"(addr));
}
__device__ __forceinline__ void ldsm4t(uint32_t* r, uint32_t addr) {
    asm volatile("ldmatrix.sync.aligned.m8n8.x4.trans.shared.b16 {%0,%1,%2,%3}, [%4];"
                 : "=r"(r[0]), "=r"(r[1]), "=r"(r[2]), "=r"(r[3]) : "r"(addr));
}
__device__ __forceinline__ void mma16816(float* c, const uint32_t* a, const uint32_t* b) {
    asm volatile(
        "mma.sync.aligned.m16n8k16.row.col.f32.f16.f16.f32 "
        "{%0,%1,%2,%3}, {%4,%5,%6,%7}, {%8,%9}, {%0,%1,%2,%3};"
        : "+f"(c[0]), "+f"(c[1]), "+f"(c[2]), "+f"(c[3])
        : "r"(a[0]), "r"(a[1]), "r"(a[2]), "r"(a[3]), "r"(b[0]), "r"(b[1]));
}

// ============================================================
// One fused fp32 -> fp16 conversion over X + all weights
// ============================================================
#define N_X  (S * HID / 4)
#define N_WQ (QDIM * HID / 4)
#define N_WK (KVDIM * HID / 4)
#define N_WV (KVDIM * HID / 4)
#define N_WO (HID * QDIM / 4)
#define N_ALL (N_X + N_WQ + N_WK + N_WV + N_WO)

__global__ void conv_all(const float* __restrict__ X,  const float* __restrict__ wq,
                         const float* __restrict__ wk, const float* __restrict__ wv,
                         const float* __restrict__ wo,
                         __half* __restrict__ Xh, __half* __restrict__ Wqkvh,
                         __half* __restrict__ Woh) {
    int i = blockIdx.x * blockDim.x + threadIdx.x;
    if (i >= N_ALL) return;
    const float* src; __half* dst; int j;
    if (i < N_X)                       { src = X;  dst = Xh;                          j = i; }
    else if (i < N_X + N_WQ)           { src = wq; dst = Wqkvh;                       j = i - N_X; }
    else if (i < N_X + N_WQ + N_WK)    { src = wk; dst = Wqkvh + QDIM * HID;          j = i - N_X - N_WQ; }
    else if (i < N_X + N_WQ + N_WK + N_WV)
                                       { src = wv; dst = Wqkvh + (QDIM + KVDIM) * HID; j = i - N_X - N_WQ - N_WK; }
    else                               { src = wo; dst = Woh;                         j = i - N_X - N_WQ - N_WK - N_WV; }
    float4 v = ((const float4*)src)[j];
    __half2* Y = (__half2*)dst;
    Y[2 * j]     = __floats2half2_rn(v.x, v.y);
    Y[2 * j + 1] = __floats2half2_rn(v.z, v.w);
}

// ============================================================
// RoPE cos/sin table
// ============================================================
__global__ void cs_table(const int* __restrict__ pos_ids, float2* __restrict__ cs) {
    const int s = blockIdx.x;
    const int d = threadIdx.x;
    float pos = (float)pos_ids[s];
    const float NL2T_64 = 19.931568569324174f / 64.0f;
    float inv = exp2f(-(float)d * NL2T_64);
    float sn, c;
    sincosf(pos * inv, &sn, &c);
    cs[s * 64 + d] = make_float2(c, sn);
}

// ============================================================
// fp16 mma.sync GEMM mainloop (shared)
// ============================================================
#define BM 128
#define BN 128
#define BK 32
#define NIT (KTOT / BK)
#define TILEB (BM * 64)
#define STAGEB (2 * TILEB)
#define NSTAGE 4
#define GSMEM (NSTAGE * STAGEB)

__device__ __forceinline__ uint32_t swz(int row, int ci) {
    return (uint32_t)(row * 64 + ((ci ^ ((row >> 1) & 3)) << 4));
}

template <typename EpiF>
__device__ __forceinline__ void gemm_core(const __half* __restrict__ A,
                                          const __half* __restrict__ B,
                                          int m0, int bn0, char* smem, EpiF epi) {
    const uint32_t sb = smem_u32(smem);
    const int tid = threadIdx.x;
    const int lane = tid & 31;
    const int w = tid >> 5;
    const int wm = w & 1;
    const int wn = w >> 1;

    const int arow_l = (lane & 7) + ((lane >> 3) & 1) * 8;
    const int ahi_c  = lane >> 4;
    const int brow_l = (lane & 7) + ((lane >> 4) & 1) * 8;
    const int bhi_c  = (lane >> 3) & 1;
    uint32_t aoff[4], boff[2];
#pragma unroll
    for (int mi = 0; mi < 4; mi++) aoff[mi] = swz(wm * 64 + mi * 16 + arow_l, ahi_c);
#pragma unroll
    for (int nt = 0; nt < 2; nt++) boff[nt] = TILEB + swz(wn * 32 + nt * 16 + brow_l, bhi_c);

    const int grow = tid >> 2;
    const int gci  = tid & 3;

    float acc[4][4][4];
#pragma unroll
    for (int mi = 0; mi < 4; mi++)
#pragma unroll
        for (int ni = 0; ni < 4; ni++)
#pragma unroll
            for (int e = 0; e < 4; e++) acc[mi][ni][e] = 0.f;

    auto load_stage = [&](int it, int buf) {
        const int k0 = it * BK;
        const uint32_t st = sb + buf * STAGEB;
#pragma unroll
        for (int p = 0; p < 2; p++) {
            int row = grow + p * 64;
            uint32_t so = swz(row, gci);
            cpasync16(st + so,         A + (size_t)(m0 + row) * KTOT + k0 + gci * 8);
            cpasync16(st + TILEB + so, B + (size_t)(bn0 + row) * KTOT + k0 + gci * 8);
        }
    };

#pragma unroll
    for (int p = 0; p < 3; p++) {
        load_stage(p, p);
        asm volatile("cp.async.commit_group;" ::: "memory");
    }

    for (int it = 0; it < NIT; it++) {
        asm volatile("cp.async.wait_group 2;" ::: "memory");
        __syncthreads();

        const uint32_t st = sb + (it & 3) * STAGEB;
#pragma unroll
        for (int kc = 0; kc < 2; kc++) {
            const uint32_t kx = kc << 5;
            uint32_t ah[4][4], bh[4][2];
#pragma unroll
            for (int mi = 0; mi < 4; mi++) ldsm4(ah[mi], st + (aoff[mi] ^ kx));
#pragma unroll
            for (int nt = 0; nt < 2; nt++) {
                uint32_t t[4];
                ldsm4(t, st + (boff[nt] ^ kx));
                bh[2 * nt][0] = t[0]; bh[2 * nt][1] = t[1];
                bh[2 * nt + 1][0] = t[2]; bh[2 * nt + 1][1] = t[3];
            }
#pragma unroll
            for (int mi = 0; mi < 4; mi++)
#pragma unroll
                for (int ni = 0; ni < 4; ni++)
                    mma16816(acc[mi][ni], ah[mi], bh[ni]);
        }
        __syncthreads();

        if (it + 3 < NIT) load_stage(it + 3, (it + 3) & 3);
        asm volatile("cp.async.commit_group;" ::: "memory");
    }

    const int lrow = wm * 64 + (lane >> 2);
    const int lcol = wn * 32 + (lane & 3) * 2;
    epi(acc, lrow, lcol);
}

// ============================================================
// fused QKV projection + RoPE + RMS epilogue for Q/K segments.
// HD == BN, so each Q/K tile is exactly one head x 128 seq rows.
// ============================================================
#define STR 136   // smem staging stride in halves (conflict-free)

__global__ __launch_bounds__(256)
void gemm_qkv(const __half* __restrict__ Xh, const __half* __restrict__ Wqkv,
              __half* __restrict__ Qh, __half* __restrict__ Kh, __half* __restrict__ Vh,
              const float* __restrict__ qnw, const float* __restrict__ knw,
              const float2* __restrict__ CS, float qscale) {
    extern __shared__ char smem[];
    const int m0 = blockIdx.y * BM;
    const int n0 = blockIdx.x * BN;

    if (n0 >= QDIM + KVDIM) {
        // ---- V segment: plain fp16 write ----
        const int vn0 = n0 - QDIM - KVDIM;
        gemm_core(Xh, Wqkv, m0, n0, smem, [&](float a[4][4][4], int lr, int lc) {
#pragma unroll
            for (int mi = 0; mi < 4; mi++)
#pragma unroll
                for (int ni = 0; ni < 4; ni++) {
                    __half* c0 = Vh + (size_t)(m0 + lr + mi * 16) * KVDIM + vn0 + lc + ni * 8;
                    *(__half2*)c0               = __floats2half2_rn(a[mi][ni][0], a[mi][ni][1]);
                    *(__half2*)(c0 + 8 * KVDIM) = __floats2half2_rn(a[mi][ni][2], a[mi][ni][3]);
                }
        });
        return;
    }

    // ---- Q or K segment: stage to smem, rope+rms, write fp16 ----
    __half* base; int stride, nn0; const float* wv_; float osc;
    if (n0 < QDIM) { base = Qh; stride = QDIM;  nn0 = n0;        wv_ = qnw; osc = qscale; }
    else           { base = Kh; stride = KVDIM; nn0 = n0 - QDIM; wv_ = knw; osc = 1.0f;   }

    gemm_core(Xh, Wqkv, m0, n0, smem, [&](float a[4][4][4], int lr, int lc) {
        __half* stg = (__half*)smem;
        __syncthreads();   // mainloop smem fully consumed
#pragma unroll
        for (int mi = 0; mi < 4; mi++)
#pragma unroll
            for (int ni = 0; ni < 4; ni++) {
                int r = lr + mi * 16;
                int c = lc + ni * 8;
                *(__half2*)&stg[r * STR + c]       = __floats2half2_rn(a[mi][ni][0], a[mi][ni][1]);
                *(__half2*)&stg[(r + 8) * STR + c] = __floats2half2_rn(a[mi][ni][2], a[mi][ni][3]);
            }
        __syncthreads();

        const int w    = threadIdx.x >> 5;
        const int lane = threadIdx.x & 31;
        float2 wa = ((const float2*)wv_)[lane];
        float2 wb = ((const float2*)wv_)[lane + 32];

#pragma unroll 4
        for (int rr = 0; rr < 16; rr++) {
            const int row = w * 16 + rr;
            const int s   = m0 + row;
            float2 cs0 = CS[s * 64 + 2 * lane];
            float2 cs1 = CS[s * 64 + 2 * lane + 1];
            float2 x1 = __half22float2(*(__half2*)&stg[row * STR + 2 * lane]);
            float2 x2 = __half22float2(*(__half2*)&stg[row * STR + 2 * lane + 64]);

            float o1x = x1.x * cs0.x - x2.x * cs0.y;
            float o1y = x1.y * cs1.x - x2.y * cs1.y;
            float o2x = x2.x * cs0.x + x1.x * cs0.y;
            float o2y = x2.y * cs1.x + x1.y * cs1.y;

            float sq = o1x * o1x + o1y * o1y + o2x * o2x + o2y * o2y;
#pragma unroll
            for (int off = 16; off; off >>= 1) sq += __shfl_xor_sync(0xffffffffu, sq, off);
            float r = rsqrtf(sq * (1.0f / 128.0f) + 1e-6f) * osc;

            __half2* y = (__half2*)(base + (size_t)s * stride + nn0);
            y[lane]      = __floats2half2_rn(o1x * r * wa.x, o1y * r * wa.y);
            y[lane + 32] = __floats2half2_rn(o2x * r * wb.x, o2y * r * wb.y);
        }
    });
}

// ---- output projection: fp32 out ----
__global__ __launch_bounds__(256)
void gemm_out(const __half* __restrict__ A, const __half* __restrict__ B,
              float* __restrict__ C) {
    extern __shared__ char smem[];
    const int m0 = blockIdx.y * BM;
    const int n0 = blockIdx.x * BN;
    gemm_core(A, B, m0, n0, smem, [&](float a[4][4][4], int lr, int lc) {
#pragma unroll
        for (int mi = 0; mi < 4; mi++)
#pragma unroll
            for (int ni = 0; ni < 4; ni++) {
                float* c0 = C + (size_t)(m0 + lr + mi * 16) * QDIM + n0 + lc + ni * 8;
                float* c1 = c0 + 8 * QDIM;
                *(float2*)c0 = make_float2(a[mi][ni][0], a[mi][ni][1]);
                *(float2*)c1 = make_float2(a[mi][ni][2], a[mi][ni][3]);
            }
    });
}

// ============================================================
// fp16 tensor-core causal GQA flash attention, 3-stage KV ring.
// Scores arrive in log2 domain (qscale includes log2 e); ex2 softmax.
// ============================================================
#define AQT 64
#define AKT 64
#define ASM_Q 0
#define ASM_KV0 16384
#define ASM_TOT (16384 + 3 * 32768)   // 114688

__device__ __forceinline__ uint32_t aswz(int row, int c) {
    return (uint32_t)(row * 256 + ((c ^ (row & 7)) << 4));
}

__global__ __launch_bounds__(128)
void attn_mma(const __half* __restrict__ Qh, const __half* __restrict__ Kh,
              const __half* __restrict__ Vh, __half* __restrict__ Ch) {
    extern __shared__ char sm[];
    const uint32_t sb = smem_u32(sm);
    const int qt = (gridDim.x - 1) - blockIdx.x;
    const int h  = blockIdx.y;
    const int kh = h >> 1;
    const int tid = threadIdx.x;
    const int lane = tid & 31;
    const int w = tid >> 5;
    const int q0 = qt * AQT;

    auto load_kv = [&](int t) {
        const int k0 = t * AKT;
        const uint32_t kb = sb + ASM_KV0 + (t % 3) * 32768;
#pragma unroll
        for (int i = 0; i < 8; i++) {
            int idx = tid + i * 128;
            int row = idx >> 4;
            int c   = idx & 15;
            cpasync16(kb + aswz(row, c),
                      Kh + (size_t)(k0 + row) * KVDIM + kh * HD + c * 8);
            cpasync16(kb + 16384 + aswz(row, c),
                      Vh + (size_t)(k0 + row) * KVDIM + kh * HD + c * 8);
        }
        asm volatile("cp.async.commit_group;" ::: "memory");
    };

#pragma unroll
    for (int i = 0; i < 8; i++) {
        int idx = tid + i * 128;
        int row = idx >> 4;
        int c   = idx & 15;
        cpasync16(sb + ASM_Q + aswz(row, c),
                  Qh + (size_t)(q0 + row) * QDIM + h * HD + c * 8);
    }
    asm volatile("cp.async.commit_group;" ::: "memory");
    load_kv(0);
    if (qt >= 1) load_kv(1);

    const int arow = (lane & 7) + ((lane >> 3) & 1) * 8;
    const int ac   = lane >> 4;
    const int brow = (lane & 7) + ((lane >> 4) & 1) * 8;
    const int bc   = (lane >> 3) & 1;
    const int vrow = (lane & 7) + ((lane >> 3) & 1) * 8;
    const int vc   = lane >> 4;
    const int r0   = lane >> 2;

    if (qt >= 1) { asm volatile("cp.async.wait_group 2;" ::: "memory"); }
    else         { asm volatile("cp.async.wait_group 1;" ::: "memory"); }
    __syncthreads();
    uint32_t qa[8][4];
#pragma unroll
    for (int kk = 0; kk < 8; kk++)
        ldsm4(qa[kk], sb + ASM_Q + aswz(16 * w + arow, kk * 2 + ac));

    float O[16][4];
#pragma unroll
    for (int nt = 0; nt < 16; nt++)
#pragma unroll
        for (int e = 0; e < 4; e++) O[nt][e] = 0.f;
    float m0 = -1e30f, m1 = -1e30f, lp0 = 0.f, lp1 = 0.f;

    for (int t = 0; t <= qt; t++) {
        if (t < qt) { asm volatile("cp.async.wait_group 1;" ::: "memory"); }
        else        { asm volatile("cp.async.wait_group 0;" ::: "memory"); }
        __syncthreads();
        if (t + 2 <= qt) load_kv(t + 2);

        const uint32_t kB = sb + ASM_KV0 + (t % 3) * 32768;
        const uint32_t vB = kB + 16384;

        float Sx[8][4];
#pragma unroll
        for (int nn = 0; nn < 8; nn++)
#pragma unroll
            for (int e = 0; e < 4; e++) Sx[nn][e] = 0.f;

#pragma unroll
        for (int kk = 0; kk < 8; kk++) {
#pragma unroll
            for (int nt = 0; nt < 4; nt++) {
                uint32_t b[4];
                ldsm4(b, kB + aswz(nt * 16 + brow, kk * 2 + bc));
                mma16816(Sx[2 * nt],     qa[kk], b);
                mma16816(Sx[2 * nt + 1], qa[kk], b + 2);
            }
        }

        if (t == qt) {
#pragma unroll
            for (int nn = 0; nn < 8; nn++)
#pragma unroll
                for (int e = 0; e < 4; e++) {
                    int col = nn * 8 + (lane & 3) * 2 + (e & 1);
                    int row = 16 * w + r0 + 8 * (e >> 1);
                    if (col > row) Sx[nn][e] = -1e30f;
                }
        }

        float t0 = -1e30f, t1 = -1e30f;
#pragma unroll
        for (int nn = 0; nn < 8; nn++) {
            t0 = fmaxf(t0, fmaxf(Sx[nn][0], Sx[nn][1]));
            t1 = fmaxf(t1, fmaxf(Sx[nn][2], Sx[nn][3]));
        }
        t0 = fmaxf(t0, __shfl_xor_sync(0xffffffffu, t0, 1));
        t0 = fmaxf(t0, __shfl_xor_sync(0xffffffffu, t0, 2));
        t1 = fmaxf(t1, __shfl_xor_sync(0xffffffffu, t1, 1));
        t1 = fmaxf(t1, __shfl_xor_sync(0xffffffffu, t1, 2));
        float n0 = fmaxf(m0, t0), n1 = fmaxf(m1, t1);
        float a0 = ex2(m0 - n0), a1 = ex2(m1 - n1);
        m0 = n0; m1 = n1; lp0 *= a0; lp1 *= a1;
#pragma unroll
        for (int nt = 0; nt < 16; nt++) {
            O[nt][0] *= a0; O[nt][1] *= a0; O[nt][2] *= a1; O[nt][3] *= a1;
        }

        uint32_t pa[4][4];
#pragma unroll
        for (int j = 0; j < 4; j++) {
            float p00 = ex2(Sx[2 * j][0] - n0),     p01 = ex2(Sx[2 * j][1] - n0);
            float p02 = ex2(Sx[2 * j][2] - n1),     p03 = ex2(Sx[2 * j][3] - n1);
            float p10 = ex2(Sx[2 * j + 1][0] - n0), p11 = ex2(Sx[2 * j + 1][1] - n0);
            float p12 = ex2(Sx[2 * j + 1][2] - n1), p13 = ex2(Sx[2 * j + 1][3] - n1);
            lp0 += p00 + p01 + p10 + p11;
            lp1 += p02 + p03 + p12 + p13;
            pa[j][0] = h2u(__floats2half2_rn(p00, p01));
            pa[j][1] = h2u(__floats2half2_rn(p02, p03));
            pa[j][2] = h2u(__floats2half2_rn(p10, p11));
            pa[j][3] = h2u(__floats2half2_rn(p12, p13));
        }

#pragma unroll
        for (int j = 0; j < 4; j++) {
#pragma unroll
            for (int g = 0; g < 8; g++) {
                uint32_t b[4];
                ldsm4t(b, vB + aswz(j * 16 + vrow, g * 2 + vc));
                mma16816(O[2 * g],     pa[j], b);
                mma16816(O[2 * g + 1], pa[j], b + 2);
            }
        }
    }

    lp0 += __shfl_xor_sync(0xffffffffu, lp0, 1);
    lp0 += __shfl_xor_sync(0xffffffffu, lp0, 2);
    lp1 += __shfl_xor_sync(0xffffffffu, lp1, 1);
    lp1 += __shfl_xor_sync(0xffffffffu, lp1, 2);
    float rl0 = 1.0f / lp0, rl1 = 1.0f / lp1;

    const int ro0 = q0 + 16 * w + r0;
    const int ro1 = ro0 + 8;
    const int colb = (lane & 3) * 2;
    __half2* C2 = (__half2*)Ch;
#pragma unroll
    for (int nt = 0; nt < 16; nt++) {
        int col = nt * 8 + colb;
        C2[((size_t)ro0 * QDIM + h * HD + col) >> 1] = __floats2half2_rn(O[nt][0] * rl0, O[nt][1] * rl0);
        C2[((size_t)ro1 * QDIM + h * HD + col) >> 1] = __floats2half2_rn(O[nt][2] * rl1, O[nt][3] * rl1);
    }
}

// ============================================================
// launch
// ============================================================
extern "C" void kernel_launch(void* const* d_in, const int* in_sizes, int n_in,
                              void* d_out, int out_size) {
    const float* X   = (const float*)d_in[0];
    const int*   pos = (const int*)d_in[2];
    const float* wq  = (const float*)d_in[3];
    const float* wk  = (const float*)d_in[4];
    const float* wv  = (const float*)d_in[5];
    const float* wo  = (const float*)d_in[6];
    const float* qnw = (const float*)d_in[7];
    const float* knw = (const float*)d_in[8];
    float* out = (float*)d_out;

    float2* CS;
    cudaGetSymbolAddress((void**)&CS, g_cs);

    __half *Xh, *Wqkvh, *Woh, *Qh, *Kh, *Vh, *Ch;
    cudaGetSymbolAddress((void**)&Xh,    g_Xh);
    cudaGetSymbolAddress((void**)&Wqkvh, g_Wqkvh);
    cudaGetSymbolAddress((void**)&Woh,   g_Woh);
    cudaGetSymbolAddress((void**)&Qh,    g_Qh);
    cudaGetSymbolAddress((void**)&Kh,    g_Kh);
    cudaGetSymbolAddress((void**)&Vh,    g_Vh);
    cudaGetSymbolAddress((void**)&Ch,    g_Ch);

    cudaFuncSetAttribute(gemm_qkv, cudaFuncAttributeMaxDynamicSharedMemorySize, GSMEM);
    cudaFuncSetAttribute(gemm_out, cudaFuncAttributeMaxDynamicSharedMemorySize, GSMEM);
    cudaFuncSetAttribute(attn_mma, cudaFuncAttributeMaxDynamicSharedMemorySize, ASM_TOT);

    const int T = 256;
    cs_table<<<S, 64>>>(pos, CS);
    conv_all<<<(N_ALL + T - 1) / T, T>>>(X, wq, wk, wv, wo, Xh, Wqkvh, Woh);

    // qscale = log2(e) / sqrt(128): softmax runs in log2 domain
    const float qscale = 0.12751744f;
    gemm_qkv<<<dim3(NQKV / BN, S / BM), 256, GSMEM>>>(Xh, Wqkvh, Qh, Kh, Vh,
                                                      qnw, knw, CS, qscale);

    attn_mma<<<dim3(S / AQT, NH), 128, ASM_TOT>>>(Qh, Kh, Vh, Ch);

    gemm_out<<<dim3(QDIM / BN, S / BM), 256, GSMEM>>>(Ch, Woh, out);
}